// round 1
// baseline (speedup 1.0000x reference)
#include <cuda_runtime.h>
#include <cuda_bf16.h>

// Problem constants
#define BATCH 4
#define SEQ   2048
#define DIM   1024
#define HEADS 8
#define DHEAD 64
#define INNER 512           // HEADS * DHEAD
#define MROWS (BATCH*SEQ)   // 8192
#define QK_SCALE 0.125f     // 64^-0.5

// ---------------- scratch (no allocation allowed) ----------------
__device__ float g_xn  [MROWS * DIM];    // 32 MB
__device__ float g_q   [MROWS * INNER];  // 16 MB
__device__ float g_kv  [MROWS * 128];    //  4 MB
__device__ float g_att [MROWS * INNER];  // 16 MB
__device__ float g_proj[MROWS * DIM];    // 32 MB

// ---------------- LayerNorm: one block per row (1024 floats) ----------------
__global__ void ln_kernel(const float* __restrict__ x,
                          const float* __restrict__ w,
                          const float* __restrict__ b,
                          float* __restrict__ out) {
    const int row = blockIdx.x;
    const int t   = threadIdx.x;            // 256 threads, 4 floats each
    const float4 v = ((const float4*)(x + (size_t)row * DIM))[t];

    float s  = v.x + v.y + v.z + v.w;
    float sq = v.x*v.x + v.y*v.y + v.z*v.z + v.w*v.w;
    #pragma unroll
    for (int m = 16; m > 0; m >>= 1) {
        s  += __shfl_xor_sync(0xffffffffu, s,  m);
        sq += __shfl_xor_sync(0xffffffffu, sq, m);
    }
    __shared__ float ss[8], ssq[8];
    const int wid = t >> 5, lane = t & 31;
    if (lane == 0) { ss[wid] = s; ssq[wid] = sq; }
    __syncthreads();
    if (wid == 0) {
        s  = (lane < 8) ? ss[lane]  : 0.f;
        sq = (lane < 8) ? ssq[lane] : 0.f;
        #pragma unroll
        for (int m = 4; m > 0; m >>= 1) {
            s  += __shfl_xor_sync(0xffffffffu, s,  m);
            sq += __shfl_xor_sync(0xffffffffu, sq, m);
        }
        if (lane == 0) { ss[0] = s; ssq[0] = sq; }
    }
    __syncthreads();
    const float mu   = ss[0] * (1.0f / DIM);
    const float var  = ssq[0] * (1.0f / DIM) - mu * mu;
    const float rstd = rsqrtf(var + 1e-5f);

    const float4 wv = ((const float4*)w)[t];
    const float4 bv = ((const float4*)b)[t];
    float4 o;
    o.x = (v.x - mu) * rstd * wv.x + bv.x;
    o.y = (v.y - mu) * rstd * wv.y + bv.y;
    o.z = (v.z - mu) * rstd * wv.z + bv.z;
    o.w = (v.w - mu) * rstd * wv.w + bv.w;
    ((float4*)(out + (size_t)row * DIM))[t] = o;
}

// ---------------- fp32 tiled GEMM: C[M,N] = alpha * A[M,K] @ B[K,N] ----------------
// BM=BN=64, BK=16, 256 threads, 4x4 micro-tile per thread.
__global__ void gemm_kernel(const float* __restrict__ A,
                            const float* __restrict__ B,
                            float* __restrict__ C,
                            int M, int N, int K, float alpha) {
    __shared__ float As[16][64];   // As[k][m]
    __shared__ float Bs[16][64];   // Bs[k][n]

    const int tid = threadIdx.x;
    const int bm = blockIdx.y * 64;
    const int bn = blockIdx.x * 64;
    const int ty = tid >> 4, tx = tid & 15;

    const int arow = tid >> 2;          // 0..63
    const int acol = (tid & 3) * 4;     // 0,4,8,12
    const int brow = tid >> 4;          // 0..15
    const int bcol = (tid & 15) * 4;    // 0..60

    float acc[4][4] = {};

    for (int k0 = 0; k0 < K; k0 += 16) {
        float4 a4 = *(const float4*)(A + (size_t)(bm + arow) * K + k0 + acol);
        As[acol + 0][arow] = a4.x;
        As[acol + 1][arow] = a4.y;
        As[acol + 2][arow] = a4.z;
        As[acol + 3][arow] = a4.w;
        float4 b4 = *(const float4*)(B + (size_t)(k0 + brow) * N + bn + bcol);
        *(float4*)&Bs[brow][bcol] = b4;
        __syncthreads();

        #pragma unroll
        for (int k = 0; k < 16; k++) {
            float4 av = *(const float4*)&As[k][ty * 4];
            float4 bv = *(const float4*)&Bs[k][tx * 4];
            float a[4] = {av.x, av.y, av.z, av.w};
            float b[4] = {bv.x, bv.y, bv.z, bv.w};
            #pragma unroll
            for (int i = 0; i < 4; i++)
                #pragma unroll
                for (int j = 0; j < 4; j++)
                    acc[i][j] = fmaf(a[i], b[j], acc[i][j]);
        }
        __syncthreads();
    }

    #pragma unroll
    for (int i = 0; i < 4; i++) {
        float4 c4 = {acc[i][0] * alpha, acc[i][1] * alpha,
                     acc[i][2] * alpha, acc[i][3] * alpha};
        *(float4*)(C + (size_t)(bm + ty * 4 + i) * N + bn + tx * 4) = c4;
    }
}

// ---------------- Flash attention (fp32, online softmax) ----------------
// grid: (SEQ/64 query tiles, BATCH*HEADS). block: 256 threads.
// K/V shared across heads (single KV head). Q already scaled by 1/8.
__global__ void attn_kernel(const float* __restrict__ Q,     // [MROWS, INNER]
                            const float* __restrict__ KV,    // [MROWS, 128]
                            float* __restrict__ O) {         // [MROWS, INNER]
    extern __shared__ float smem[];
    float* QsT = smem;                 // [d][row]   64x64
    float* KsT = smem + 64 * 64;       // [d][key]   64x64
    float* Vs  = smem + 2 * 64 * 64;   // [key][d]   64x64
    float* PsT = smem + 3 * 64 * 64;   // [key][row] 64x64

    const int qt = blockIdx.x;
    const int bh = blockIdx.y;
    const int b  = bh >> 3, h = bh & 7;
    const int tid = threadIdx.x;
    const int ty = tid >> 4, tx = tid & 15;
    const int lrow = tid >> 4;          // 0..15
    const int ld0  = (tid & 15) * 4;    // 0..60

    const int qrow0 = b * SEQ + qt * 64;
    const int krow0 = b * SEQ;

    // load Q tile, transposed into QsT[d][row]
    #pragma unroll
    for (int r = 0; r < 4; r++) {
        int row = lrow + r * 16;
        float4 q4 = *(const float4*)(Q + (size_t)(qrow0 + row) * INNER + h * DHEAD + ld0);
        QsT[(ld0 + 0) * 64 + row] = q4.x;
        QsT[(ld0 + 1) * 64 + row] = q4.y;
        QsT[(ld0 + 2) * 64 + row] = q4.z;
        QsT[(ld0 + 3) * 64 + row] = q4.w;
    }

    float o[4][4] = {};
    float m[4], l[4];
    #pragma unroll
    for (int i = 0; i < 4; i++) { m[i] = -1e30f; l[i] = 0.f; }

    for (int kt = 0; kt < SEQ / 64; kt++) {
        __syncthreads();   // prev-iter PsT/Vs reads done; Q visible on first iter
        // load K (transposed) and V tiles
        #pragma unroll
        for (int r = 0; r < 4; r++) {
            int key = lrow + r * 16;
            const float* src = KV + (size_t)(krow0 + kt * 64 + key) * 128;
            float4 k4 = *(const float4*)(src + ld0);
            KsT[(ld0 + 0) * 64 + key] = k4.x;
            KsT[(ld0 + 1) * 64 + key] = k4.y;
            KsT[(ld0 + 2) * 64 + key] = k4.z;
            KsT[(ld0 + 3) * 64 + key] = k4.w;
            float4 v4 = *(const float4*)(src + 64 + ld0);
            *(float4*)(Vs + key * 64 + ld0) = v4;
        }
        __syncthreads();

        // S = Q @ K^T   (thread: rows ty*4.., cols tx*4..)
        float s[4][4] = {};
        #pragma unroll 16
        for (int d = 0; d < 64; d++) {
            float4 qv = *(const float4*)(QsT + d * 64 + ty * 4);
            float4 kv4 = *(const float4*)(KsT + d * 64 + tx * 4);
            float qa[4] = {qv.x, qv.y, qv.z, qv.w};
            float kb[4] = {kv4.x, kv4.y, kv4.z, kv4.w};
            #pragma unroll
            for (int i = 0; i < 4; i++)
                #pragma unroll
                for (int j = 0; j < 4; j++)
                    s[i][j] = fmaf(qa[i], kb[j], s[i][j]);
        }

        // online softmax (reduce across the 16-lane tx group)
        #pragma unroll
        for (int i = 0; i < 4; i++) {
            float rmax = fmaxf(fmaxf(s[i][0], s[i][1]), fmaxf(s[i][2], s[i][3]));
            #pragma unroll
            for (int msk = 8; msk > 0; msk >>= 1)
                rmax = fmaxf(rmax, __shfl_xor_sync(0xffffffffu, rmax, msk));
            float mn = fmaxf(m[i], rmax);
            float corr = __expf(m[i] - mn);
            m[i] = mn;
            float rsum = 0.f;
            #pragma unroll
            for (int j = 0; j < 4; j++) {
                s[i][j] = __expf(s[i][j] - mn);
                rsum += s[i][j];
            }
            #pragma unroll
            for (int msk = 8; msk > 0; msk >>= 1)
                rsum += __shfl_xor_sync(0xffffffffu, rsum, msk);
            l[i] = l[i] * corr + rsum;
            #pragma unroll
            for (int j = 0; j < 4; j++) o[i][j] *= corr;
        }

        // store P transposed: PsT[col c][row]
        #pragma unroll
        for (int i = 0; i < 4; i++)
            #pragma unroll
            for (int j = 0; j < 4; j++)
                PsT[(tx * 4 + j) * 64 + (ty * 4 + i)] = s[i][j];
        __syncthreads();

        // O += P @ V
        #pragma unroll 16
        for (int c = 0; c < 64; c++) {
            float4 pv = *(const float4*)(PsT + c * 64 + ty * 4);
            float4 vv = *(const float4*)(Vs + c * 64 + tx * 4);
            float pa[4] = {pv.x, pv.y, pv.z, pv.w};
            float vb[4] = {vv.x, vv.y, vv.z, vv.w};
            #pragma unroll
            for (int i = 0; i < 4; i++)
                #pragma unroll
                for (int j = 0; j < 4; j++)
                    o[i][j] = fmaf(pa[i], vb[j], o[i][j]);
        }
    }

    // epilogue: normalize & write [row, h*64 + col]
    #pragma unroll
    for (int i = 0; i < 4; i++) {
        float inv = 1.0f / l[i];
        float4 out4 = {o[i][0] * inv, o[i][1] * inv, o[i][2] * inv, o[i][3] * inv};
        *(float4*)(O + (size_t)(qrow0 + ty * 4 + i) * INNER + h * DHEAD + tx * 4) = out4;
    }
}

// ---------------- launch ----------------
extern "C" void kernel_launch(void* const* d_in, const int* in_sizes, int n_in,
                              void* d_out, int out_size) {
    const float* x   = (const float*)d_in[0];
    const float* Wq  = (const float*)d_in[1];
    const float* Wkv = (const float*)d_in[2];
    const float* Wo  = (const float*)d_in[3];
    const float* nw  = (const float*)d_in[4];
    const float* nb  = (const float*)d_in[5];
    const float* onw = (const float*)d_in[6];
    const float* onb = (const float*)d_in[7];
    float* out = (float*)d_out;

    float *xn, *q, *kv, *att, *proj;
    cudaGetSymbolAddress((void**)&xn,   g_xn);
    cudaGetSymbolAddress((void**)&q,    g_q);
    cudaGetSymbolAddress((void**)&kv,   g_kv);
    cudaGetSymbolAddress((void**)&att,  g_att);
    cudaGetSymbolAddress((void**)&proj, g_proj);

    const int attn_smem = 4 * 64 * 64 * sizeof(float);  // 64 KB
    cudaFuncSetAttribute(attn_kernel, cudaFuncAttributeMaxDynamicSharedMemorySize, attn_smem);

    // 1) pre-LN
    ln_kernel<<<MROWS, 256>>>(x, nw, nb, xn);
    // 2) Q = xn @ Wq * (1/8);  KV = xn @ Wkv
    gemm_kernel<<<dim3(INNER / 64, MROWS / 64), 256>>>(xn, Wq, q, MROWS, INNER, DIM, QK_SCALE);
    gemm_kernel<<<dim3(128 / 64,  MROWS / 64), 256>>>(xn, Wkv, kv, MROWS, 128, DIM, 1.0f);
    // 3) flash attention
    attn_kernel<<<dim3(SEQ / 64, BATCH * HEADS), 256, attn_smem>>>(q, kv, att);
    // 4) out-projection
    gemm_kernel<<<dim3(DIM / 64, MROWS / 64), 256>>>(att, Wo, proj, MROWS, DIM, INNER, 1.0f);
    // 5) post-LN
    ln_kernel<<<MROWS, 256>>>(proj, onw, onb, out);
}

// round 4
// speedup vs baseline: 3.0929x; 3.0929x over previous
#include <cuda_runtime.h>
#include <cuda_bf16.h>
#include <cuda_fp16.h>
#include <cstdint>

#define BATCH 4
#define SEQ   2048
#define DIM   1024
#define HEADS 8
#define DHEAD 64
#define INNER 512
#define MROWS 8192
#define NQKV  640            // 512 (Q) + 64 (K) + 64 (V)
#define QK_SCALE 0.125f

typedef __nv_bfloat16 bf16;

// ---------------- scratch ----------------
__device__ bf16  g_xnh [MROWS * DIM];
__device__ bf16  g_xnl [MROWS * DIM];
__device__ float g_qkv [MROWS * NQKV];
__device__ bf16  g_atth[MROWS * INNER];
__device__ bf16  g_attl[MROWS * INNER];
__device__ float g_proj[MROWS * DIM];
__device__ bf16  g_w1h [NQKV * DIM], g_w1l [NQKV * DIM];   // [n][k] rows: Wq^T*s | Wkv^T
__device__ bf16  g_woh [DIM * INNER], g_wol [DIM * INNER]; // [n][k]

// ---------------- helpers ----------------
__device__ __forceinline__ uint32_t smem_u32(const void* p) {
    uint32_t a;
    asm("{ .reg .u64 t; cvta.to.shared.u64 t, %1; cvt.u32.u64 %0, t; }" : "=r"(a) : "l"(p));
    return a;
}
__device__ __forceinline__ void ldsm4(uint32_t* r, uint32_t a) {
    asm volatile("ldmatrix.sync.aligned.m8n8.x4.shared.b16 {%0,%1,%2,%3}, [%4];"
                 : "=r"(r[0]), "=r"(r[1]), "=r"(r[2]), "=r"(r[3]) : "r"(a));
}
__device__ __forceinline__ void ldsm4t(uint32_t* r, uint32_t a) {
    asm volatile("ldmatrix.sync.aligned.m8n8.x4.trans.shared.b16 {%0,%1,%2,%3}, [%4];"
                 : "=r"(r[0]), "=r"(r[1]), "=r"(r[2]), "=r"(r[3]) : "r"(a));
}
__device__ __forceinline__ void mma16816(float* d, const uint32_t* a, const uint32_t* b) {
    asm volatile(
        "mma.sync.aligned.m16n8k16.row.col.f32.bf16.bf16.f32 "
        "{%0,%1,%2,%3}, {%4,%5,%6,%7}, {%8,%9}, {%0,%1,%2,%3};"
        : "+f"(d[0]), "+f"(d[1]), "+f"(d[2]), "+f"(d[3])
        : "r"(a[0]), "r"(a[1]), "r"(a[2]), "r"(a[3]), "r"(b[0]), "r"(b[1]));
}
__device__ __forceinline__ void mma16816h(float* d, const uint32_t* a, const uint32_t* b) {
    asm volatile(
        "mma.sync.aligned.m16n8k16.row.col.f32.f16.f16.f32 "
        "{%0,%1,%2,%3}, {%4,%5,%6,%7}, {%8,%9}, {%0,%1,%2,%3};"
        : "+f"(d[0]), "+f"(d[1]), "+f"(d[2]), "+f"(d[3])
        : "r"(a[0]), "r"(a[1]), "r"(a[2]), "r"(a[3]), "r"(b[0]), "r"(b[1]));
}
__device__ __forceinline__ uint32_t packh(float lo, float hi) {
    uint32_t r;
    asm("cvt.rn.f16x2.f32 %0, %1, %2;" : "=r"(r) : "f"(hi), "f"(lo));  // hi->upper, lo->lower
    return r;
}

// ---------------- LayerNorm (fp32 out) ----------------
__global__ void ln_kernel(const float* __restrict__ x, const float* __restrict__ w,
                          const float* __restrict__ b, float* __restrict__ out) {
    const int row = blockIdx.x, t = threadIdx.x;
    const float4 v = ((const float4*)(x + (size_t)row * DIM))[t];
    float s = v.x + v.y + v.z + v.w;
    float sq = v.x*v.x + v.y*v.y + v.z*v.z + v.w*v.w;
    #pragma unroll
    for (int m = 16; m > 0; m >>= 1) {
        s += __shfl_xor_sync(~0u, s, m);  sq += __shfl_xor_sync(~0u, sq, m);
    }
    __shared__ float ss[8], ssq[8];
    const int wid = t >> 5, lane = t & 31;
    if (lane == 0) { ss[wid] = s; ssq[wid] = sq; }
    __syncthreads();
    if (wid == 0) {
        s = (lane < 8) ? ss[lane] : 0.f;  sq = (lane < 8) ? ssq[lane] : 0.f;
        #pragma unroll
        for (int m = 4; m > 0; m >>= 1) {
            s += __shfl_xor_sync(~0u, s, m);  sq += __shfl_xor_sync(~0u, sq, m);
        }
        if (lane == 0) { ss[0] = s; ssq[0] = sq; }
    }
    __syncthreads();
    const float mu = ss[0] * (1.0f / DIM);
    const float rstd = rsqrtf(ssq[0] * (1.0f / DIM) - mu * mu + 1e-5f);
    const float4 wv = ((const float4*)w)[t];
    const float4 bv = ((const float4*)b)[t];
    float4 o;
    o.x = (v.x - mu) * rstd * wv.x + bv.x;  o.y = (v.y - mu) * rstd * wv.y + bv.y;
    o.z = (v.z - mu) * rstd * wv.z + bv.z;  o.w = (v.w - mu) * rstd * wv.w + bv.w;
    ((float4*)(out + (size_t)row * DIM))[t] = o;
}

// ---------------- LayerNorm -> split bf16 ----------------
__global__ void ln_split_kernel(const float* __restrict__ x, const float* __restrict__ w,
                                const float* __restrict__ b,
                                bf16* __restrict__ oh, bf16* __restrict__ ol) {
    const int row = blockIdx.x, t = threadIdx.x;
    const float4 v = ((const float4*)(x + (size_t)row * DIM))[t];
    float s = v.x + v.y + v.z + v.w;
    float sq = v.x*v.x + v.y*v.y + v.z*v.z + v.w*v.w;
    #pragma unroll
    for (int m = 16; m > 0; m >>= 1) {
        s += __shfl_xor_sync(~0u, s, m);  sq += __shfl_xor_sync(~0u, sq, m);
    }
    __shared__ float ss[8], ssq[8];
    const int wid = t >> 5, lane = t & 31;
    if (lane == 0) { ss[wid] = s; ssq[wid] = sq; }
    __syncthreads();
    if (wid == 0) {
        s = (lane < 8) ? ss[lane] : 0.f;  sq = (lane < 8) ? ssq[lane] : 0.f;
        #pragma unroll
        for (int m = 4; m > 0; m >>= 1) {
            s += __shfl_xor_sync(~0u, s, m);  sq += __shfl_xor_sync(~0u, sq, m);
        }
        if (lane == 0) { ss[0] = s; ssq[0] = sq; }
    }
    __syncthreads();
    const float mu = ss[0] * (1.0f / DIM);
    const float rstd = rsqrtf(ssq[0] * (1.0f / DIM) - mu * mu + 1e-5f);
    const float4 wv = ((const float4*)w)[t];
    const float4 bv = ((const float4*)b)[t];
    float o[4];
    o[0] = (v.x - mu) * rstd * wv.x + bv.x;  o[1] = (v.y - mu) * rstd * wv.y + bv.y;
    o[2] = (v.z - mu) * rstd * wv.z + bv.z;  o[3] = (v.w - mu) * rstd * wv.w + bv.w;
    size_t base = (size_t)row * DIM + t * 4;
    #pragma unroll
    for (int j = 0; j < 4; j += 2) {
        bf16 h0 = __float2bfloat16(o[j]),     h1 = __float2bfloat16(o[j + 1]);
        bf16 l0 = __float2bfloat16(o[j] - __bfloat162float(h0));
        bf16 l1 = __float2bfloat16(o[j + 1] - __bfloat162float(h1));
        *(__nv_bfloat162*)(oh + base + j) = __halves2bfloat162(h0, h1);
        *(__nv_bfloat162*)(ol + base + j) = __halves2bfloat162(l0, l1);
    }
}

// ---------------- weight transpose + split (+scale): W[K,N] -> T[n][k] ----------------
__global__ void wtrans_kernel(const float* __restrict__ W, bf16* __restrict__ Th,
                              bf16* __restrict__ Tl, int K, int N, float scale) {
    __shared__ float tile[32][33];
    const int n0 = blockIdx.x * 32, k0 = blockIdx.y * 32;
    const int tx = threadIdx.x, ty = threadIdx.y;   // 32x8
    #pragma unroll
    for (int j = 0; j < 4; j++)
        tile[ty + 8 * j][tx] = W[(size_t)(k0 + ty + 8 * j) * N + n0 + tx];
    __syncthreads();
    #pragma unroll
    for (int j = 0; j < 4; j++) {
        float v = tile[tx][ty + 8 * j] * scale;
        bf16 h = __float2bfloat16(v);
        bf16 l = __float2bfloat16(v - __bfloat162float(h));
        size_t idx = (size_t)(n0 + ty + 8 * j) * K + k0 + tx;
        Th[idx] = h;  Tl[idx] = l;
    }
}

// ---------------- HMMA split-bf16 GEMM: C[M,N] = A @ B^T ----------------
// A hi/lo [M][K], B hi/lo [N][K] bf16. Tile 128x128x64, 256 threads.
#define GP 72   // padded smem row (bf16)
#define GEMM_SMEM (4 * 128 * GP * 2)

__global__ __launch_bounds__(256, 1)
void gemm_hmma(const bf16* __restrict__ Ah, const bf16* __restrict__ Al,
               const bf16* __restrict__ Bh, const bf16* __restrict__ Bl,
               float* __restrict__ C, int N, int K) {
    extern __shared__ bf16 sm[];
    bf16* sAh = sm;             bf16* sAl = sm + 128 * GP;
    bf16* sBh = sm + 256 * GP;  bf16* sBl = sm + 384 * GP;

    const int tid = threadIdx.x, lane = tid & 31, wid = tid >> 5;
    const int wm = wid >> 1, wn = wid & 1;
    const int bm = blockIdx.y * 128, bn = blockIdx.x * 128;
    const uint32_t sb = smem_u32(sm);
    const uint32_t oAh = 0, oAl = 128 * GP * 2, oBh = 256 * GP * 2, oBl = 384 * GP * 2;

    float d[2][8][4] = {};

    const int a_r = wm * 32 + (lane & 15), a_c = (lane >> 4) * 8;
    const int b_r = wn * 64 + (lane >> 4) * 8 + (lane & 7), b_c = ((lane >> 3) & 1) * 8;

    for (int k0 = 0; k0 < K; k0 += 64) {
        __syncthreads();
        #pragma unroll
        for (int i = 0; i < 4; i++) {
            int idx = tid + i * 256, r = idx >> 3, c = (idx & 7) * 8;
            *(uint4*)(sAh + r * GP + c) = *(const uint4*)(Ah + (size_t)(bm + r) * K + k0 + c);
            *(uint4*)(sAl + r * GP + c) = *(const uint4*)(Al + (size_t)(bm + r) * K + k0 + c);
            *(uint4*)(sBh + r * GP + c) = *(const uint4*)(Bh + (size_t)(bn + r) * K + k0 + c);
            *(uint4*)(sBl + r * GP + c) = *(const uint4*)(Bl + (size_t)(bn + r) * K + k0 + c);
        }
        __syncthreads();

        #pragma unroll
        for (int ks = 0; ks < 4; ks++) {
            uint32_t aH[2][4], aL[2][4];
            #pragma unroll
            for (int mi = 0; mi < 2; mi++) {
                uint32_t off = (uint32_t)((a_r + mi * 16) * GP + ks * 16 + a_c) * 2;
                ldsm4(aH[mi], sb + oAh + off);
                ldsm4(aL[mi], sb + oAl + off);
            }
            #pragma unroll
            for (int jp = 0; jp < 4; jp++) {
                uint32_t bH[4], bL[4];
                uint32_t off = (uint32_t)((jp * 16 + b_r) * GP + ks * 16 + b_c) * 2;
                ldsm4(bH, sb + oBh + off);
                ldsm4(bL, sb + oBl + off);
                #pragma unroll
                for (int mi = 0; mi < 2; mi++) {
                    mma16816(d[mi][2 * jp],     aH[mi], bH);
                    mma16816(d[mi][2 * jp],     aH[mi], bL);
                    mma16816(d[mi][2 * jp],     aL[mi], bH);
                    mma16816(d[mi][2 * jp + 1], aH[mi], bH + 2);
                    mma16816(d[mi][2 * jp + 1], aH[mi], bL + 2);
                    mma16816(d[mi][2 * jp + 1], aL[mi], bH + 2);
                }
            }
        }
    }

    #pragma unroll
    for (int mi = 0; mi < 2; mi++) {
        int row = bm + wm * 32 + mi * 16 + (lane >> 2);
        #pragma unroll
        for (int jt = 0; jt < 8; jt++) {
            int col = bn + wn * 64 + jt * 8 + (lane & 3) * 2;
            *(float2*)(C + (size_t)row * N + col)       = make_float2(d[mi][jt][0], d[mi][jt][1]);
            *(float2*)(C + (size_t)(row + 8) * N + col) = make_float2(d[mi][jt][2], d[mi][jt][3]);
        }
    }
}

// ---------------- HMMA flash attention ----------------
// grid (SEQ/128, BATCH*HEADS), 256 threads (8 warps x 16 q-rows).
// smem bf16 elems: QH 0, QL 9216, KH 18432, KL 23040, VB(fp16) 27648 (rows padded to 72)
#define ATTN_SMEM (32256 * 2)

__global__ __launch_bounds__(256, 1)
void attn_hmma(const float* __restrict__ QKV,
               bf16* __restrict__ Oh, bf16* __restrict__ Ol) {
    extern __shared__ bf16 sm[];
    bf16* QH = sm;          bf16* QL = sm + 9216;
    bf16* KH = sm + 18432;  bf16* KL = sm + 23040;
    __half* VB = (__half*)(sm + 27648);

    const int tid = threadIdx.x, lane = tid & 31, wid = tid >> 5;
    const int qt = blockIdx.x, bh = blockIdx.y;
    const int b = bh >> 3, h = bh & 7;
    const int qrow0 = b * SEQ + qt * 128;
    const int krow0 = b * SEQ;
    const uint32_t sb = smem_u32(sm);
    const uint32_t oQH = 0, oQL = 9216 * 2, oKH = 18432 * 2, oKL = 23040 * 2, oVB = 27648 * 2;

    // load Q tile (128 x 64 fp32) -> split bf16
    #pragma unroll
    for (int i = 0; i < 8; i++) {
        int idx = tid + i * 256, r = idx >> 4, c = (idx & 15) * 4;
        float4 v = *(const float4*)(QKV + (size_t)(qrow0 + r) * NQKV + h * DHEAD + c);
        float vv[4] = {v.x, v.y, v.z, v.w};
        #pragma unroll
        for (int j = 0; j < 4; j += 2) {
            bf16 h0 = __float2bfloat16(vv[j]), h1 = __float2bfloat16(vv[j + 1]);
            bf16 l0 = __float2bfloat16(vv[j] - __bfloat162float(h0));
            bf16 l1 = __float2bfloat16(vv[j + 1] - __bfloat162float(h1));
            *(__nv_bfloat162*)(QH + r * GP + c + j) = __halves2bfloat162(h0, h1);
            *(__nv_bfloat162*)(QL + r * GP + c + j) = __halves2bfloat162(l0, l1);
        }
    }

    const int rbase = wid * 16;
    const int a_r = rbase + (lane & 15), a_c = (lane >> 4) * 8;
    const int b_r = (lane >> 4) * 8 + (lane & 7), b_c = ((lane >> 3) & 1) * 8;
    const int v_r = ((lane >> 3) & 1) * 8 + (lane & 7), v_c = (lane >> 4) * 8;

    float o[8][4] = {};
    float mreg[2] = {-1e30f, -1e30f}, lreg[2] = {0.f, 0.f};

    for (int kt = 0; kt < SEQ / 64; kt++) {
        __syncthreads();
        // load K (split bf16) + V (fp16) : 64 rows x 128 fp32
        #pragma unroll
        for (int i = 0; i < 8; i++) {
            int idx = tid + i * 256, r = idx >> 5, c = (idx & 31) * 4;
            float4 v = *(const float4*)(QKV + (size_t)(krow0 + kt * 64 + r) * NQKV + 512 + c);
            float vv[4] = {v.x, v.y, v.z, v.w};
            if (c < 64) {
                #pragma unroll
                for (int j = 0; j < 4; j += 2) {
                    bf16 h0 = __float2bfloat16(vv[j]), h1 = __float2bfloat16(vv[j + 1]);
                    bf16 l0 = __float2bfloat16(vv[j] - __bfloat162float(h0));
                    bf16 l1 = __float2bfloat16(vv[j + 1] - __bfloat162float(h1));
                    *(__nv_bfloat162*)(KH + r * GP + c + j) = __halves2bfloat162(h0, h1);
                    *(__nv_bfloat162*)(KL + r * GP + c + j) = __halves2bfloat162(l0, l1);
                }
            } else {
                int cc = c - 64;
                #pragma unroll
                for (int j = 0; j < 4; j += 2)
                    *(__half2*)(VB + r * GP + cc + j) =
                        __floats2half2_rn(vv[j], vv[j + 1]);
            }
        }
        __syncthreads();

        // S = Q @ K^T (split-bf16, 3 products)
        float s[8][4] = {};
        #pragma unroll
        for (int dk = 0; dk < 4; dk++) {
            uint32_t aH[4], aL[4];
            uint32_t aoff = (uint32_t)(a_r * GP + dk * 16 + a_c) * 2;
            ldsm4(aH, sb + oQH + aoff);
            ldsm4(aL, sb + oQL + aoff);
            #pragma unroll
            for (int jp = 0; jp < 4; jp++) {
                uint32_t bH[4], bL[4];
                uint32_t koff = (uint32_t)((jp * 16 + b_r) * GP + dk * 16 + b_c) * 2;
                ldsm4(bH, sb + oKH + koff);
                ldsm4(bL, sb + oKL + koff);
                mma16816(s[2 * jp],     aH, bH);
                mma16816(s[2 * jp],     aH, bL);
                mma16816(s[2 * jp],     aL, bH);
                mma16816(s[2 * jp + 1], aH, bH + 2);
                mma16816(s[2 * jp + 1], aH, bL + 2);
                mma16816(s[2 * jp + 1], aL, bH + 2);
            }
        }

        // online softmax (rows live in-warp; reduce across quad lanes)
        #pragma unroll
        for (int e = 0; e < 2; e++) {
            float rmax = -1e30f;
            #pragma unroll
            for (int jt = 0; jt < 8; jt++)
                rmax = fmaxf(rmax, fmaxf(s[jt][2 * e], s[jt][2 * e + 1]));
            rmax = fmaxf(rmax, __shfl_xor_sync(~0u, rmax, 1));
            rmax = fmaxf(rmax, __shfl_xor_sync(~0u, rmax, 2));
            float mn = fmaxf(mreg[e], rmax);
            float corr = __expf(mreg[e] - mn);
            mreg[e] = mn;
            float rsum = 0.f;
            #pragma unroll
            for (int jt = 0; jt < 8; jt++) {
                s[jt][2 * e]     = __expf(s[jt][2 * e] - mn);
                s[jt][2 * e + 1] = __expf(s[jt][2 * e + 1] - mn);
                rsum += s[jt][2 * e] + s[jt][2 * e + 1];
            }
            rsum += __shfl_xor_sync(~0u, rsum, 1);
            rsum += __shfl_xor_sync(~0u, rsum, 2);
            lreg[e] = lreg[e] * corr + rsum;
            #pragma unroll
            for (int jt = 0; jt < 8; jt++) { o[jt][2 * e] *= corr; o[jt][2 * e + 1] *= corr; }
        }

        // O += P @ V  (fp16: P repacked in-register, V via ldmatrix.trans)
        #pragma unroll
        for (int kk = 0; kk < 4; kk++) {
            uint32_t aP[4] = {
                packh(s[2 * kk][0],     s[2 * kk][1]),
                packh(s[2 * kk][2],     s[2 * kk][3]),
                packh(s[2 * kk + 1][0], s[2 * kk + 1][1]),
                packh(s[2 * kk + 1][2], s[2 * kk + 1][3])
            };
            #pragma unroll
            for (int dp = 0; dp < 4; dp++) {
                uint32_t bV[4];
                ldsm4t(bV, sb + oVB + (uint32_t)((kk * 16 + v_r) * GP + dp * 16 + v_c) * 2);
                mma16816h(o[2 * dp],     aP, bV);
                mma16816h(o[2 * dp + 1], aP, bV + 2);
            }
        }
    }

    // epilogue: normalize, split-bf16 store to [row][h*64+d]
    #pragma unroll
    for (int e = 0; e < 2; e++) {
        float inv = 1.0f / lreg[e];
        int row = qrow0 + rbase + (lane >> 2) + 8 * e;
        #pragma unroll
        for (int dd = 0; dd < 8; dd++) {
            float v0 = o[dd][2 * e] * inv, v1 = o[dd][2 * e + 1] * inv;
            bf16 h0 = __float2bfloat16(v0), h1 = __float2bfloat16(v1);
            bf16 l0 = __float2bfloat16(v0 - __bfloat162float(h0));
            bf16 l1 = __float2bfloat16(v1 - __bfloat162float(h1));
            size_t base = (size_t)row * INNER + h * DHEAD + dd * 8 + (lane & 3) * 2;
            *(__nv_bfloat162*)(Oh + base) = __halves2bfloat162(h0, h1);
            *(__nv_bfloat162*)(Ol + base) = __halves2bfloat162(l0, l1);
        }
    }
}

// ---------------- launch ----------------
extern "C" void kernel_launch(void* const* d_in, const int* in_sizes, int n_in,
                              void* d_out, int out_size) {
    const float* x   = (const float*)d_in[0];
    const float* Wq  = (const float*)d_in[1];
    const float* Wkv = (const float*)d_in[2];
    const float* Wo  = (const float*)d_in[3];
    const float* nw  = (const float*)d_in[4];
    const float* nb  = (const float*)d_in[5];
    const float* onw = (const float*)d_in[6];
    const float* onb = (const float*)d_in[7];
    float* out = (float*)d_out;

    bf16 *xnh, *xnl, *atth, *attl, *w1h, *w1l, *woh, *wol;
    float *qkv, *proj;
    cudaGetSymbolAddress((void**)&xnh,  g_xnh);
    cudaGetSymbolAddress((void**)&xnl,  g_xnl);
    cudaGetSymbolAddress((void**)&qkv,  g_qkv);
    cudaGetSymbolAddress((void**)&atth, g_atth);
    cudaGetSymbolAddress((void**)&attl, g_attl);
    cudaGetSymbolAddress((void**)&proj, g_proj);
    cudaGetSymbolAddress((void**)&w1h,  g_w1h);
    cudaGetSymbolAddress((void**)&w1l,  g_w1l);
    cudaGetSymbolAddress((void**)&woh,  g_woh);
    cudaGetSymbolAddress((void**)&wol,  g_wol);

    cudaFuncSetAttribute(gemm_hmma, cudaFuncAttributeMaxDynamicSharedMemorySize, GEMM_SMEM);
    cudaFuncSetAttribute(attn_hmma, cudaFuncAttributeMaxDynamicSharedMemorySize, ATTN_SMEM);

    // weight transpose + split (+fold QK scale into Wq)
    wtrans_kernel<<<dim3(INNER / 32, DIM / 32), dim3(32, 8)>>>(Wq, w1h, w1l, DIM, INNER, QK_SCALE);
    wtrans_kernel<<<dim3(128 / 32, DIM / 32), dim3(32, 8)>>>(Wkv, w1h + (size_t)512 * DIM,
                                                             w1l + (size_t)512 * DIM, DIM, 128, 1.0f);
    wtrans_kernel<<<dim3(DIM / 32, INNER / 32), dim3(32, 8)>>>(Wo, woh, wol, INNER, DIM, 1.0f);

    // 1) pre-LN -> split bf16
    ln_split_kernel<<<MROWS, 256>>>(x, nw, nb, xnh, xnl);
    // 2) merged QKV GEMM: [8192,640] = xn @ [Wq*s | Wkv]
    gemm_hmma<<<dim3(NQKV / 128, MROWS / 128), 256, GEMM_SMEM>>>(xnh, xnl, w1h, w1l, qkv, NQKV, DIM);
    // 3) flash attention
    attn_hmma<<<dim3(SEQ / 128, BATCH * HEADS), 256, ATTN_SMEM>>>(qkv, atth, attl);
    // 4) out-projection
    gemm_hmma<<<dim3(DIM / 128, MROWS / 128), 256, GEMM_SMEM>>>(atth, attl, woh, wol, proj, DIM, INNER);
    // 5) post-LN
    ln_kernel<<<MROWS, 256>>>(proj, onw, onb, out);
}

// round 5
// speedup vs baseline: 3.9706x; 1.2838x over previous
#include <cuda_runtime.h>
#include <cuda_bf16.h>
#include <cuda_fp16.h>
#include <cstdint>

#define BATCH 4
#define SEQ   2048
#define DIM   1024
#define HEADS 8
#define DHEAD 64
#define INNER 512
#define MROWS 8192
#define NQKV  640            // 512 (Q) + 64 (K) + 64 (V)
#define QK_SCALE 0.125f

typedef __nv_bfloat16 bf16;

// ---------------- scratch ----------------
__device__ bf16   g_xnh [MROWS * DIM];
__device__ bf16   g_xnl [MROWS * DIM];
__device__ float  g_qkv [MROWS * NQKV];
__device__ bf16   g_qh  [MROWS * INNER], g_ql [MROWS * INNER];
__device__ bf16   g_kh  [MROWS * DHEAD], g_kl [MROWS * DHEAD];
__device__ __half g_vh  [MROWS * DHEAD];
__device__ bf16   g_atth[MROWS * INNER];
__device__ bf16   g_attl[MROWS * INNER];
__device__ float  g_proj[MROWS * DIM];
__device__ bf16   g_w1h [NQKV * DIM], g_w1l [NQKV * DIM];   // [n][k]: Wq^T*s | Wkv^T
__device__ bf16   g_woh [DIM * INNER], g_wol [DIM * INNER]; // [n][k]

// ---------------- helpers ----------------
__device__ __forceinline__ uint32_t smem_u32(const void* p) {
    uint32_t a;
    asm("{ .reg .u64 t; cvta.to.shared.u64 t, %1; cvt.u32.u64 %0, t; }" : "=r"(a) : "l"(p));
    return a;
}
__device__ __forceinline__ void ldsm4(uint32_t* r, uint32_t a) {
    asm volatile("ldmatrix.sync.aligned.m8n8.x4.shared.b16 {%0,%1,%2,%3}, [%4];"
                 : "=r"(r[0]), "=r"(r[1]), "=r"(r[2]), "=r"(r[3]) : "r"(a));
}
__device__ __forceinline__ void ldsm4t(uint32_t* r, uint32_t a) {
    asm volatile("ldmatrix.sync.aligned.m8n8.x4.trans.shared.b16 {%0,%1,%2,%3}, [%4];"
                 : "=r"(r[0]), "=r"(r[1]), "=r"(r[2]), "=r"(r[3]) : "r"(a));
}
__device__ __forceinline__ void mma16816(float* d, const uint32_t* a, const uint32_t* b) {
    asm volatile(
        "mma.sync.aligned.m16n8k16.row.col.f32.bf16.bf16.f32 "
        "{%0,%1,%2,%3}, {%4,%5,%6,%7}, {%8,%9}, {%0,%1,%2,%3};"
        : "+f"(d[0]), "+f"(d[1]), "+f"(d[2]), "+f"(d[3])
        : "r"(a[0]), "r"(a[1]), "r"(a[2]), "r"(a[3]), "r"(b[0]), "r"(b[1]));
}
__device__ __forceinline__ void mma16816h(float* d, const uint32_t* a, const uint32_t* b) {
    asm volatile(
        "mma.sync.aligned.m16n8k16.row.col.f32.f16.f16.f32 "
        "{%0,%1,%2,%3}, {%4,%5,%6,%7}, {%8,%9}, {%0,%1,%2,%3};"
        : "+f"(d[0]), "+f"(d[1]), "+f"(d[2]), "+f"(d[3])
        : "r"(a[0]), "r"(a[1]), "r"(a[2]), "r"(a[3]), "r"(b[0]), "r"(b[1]));
}
__device__ __forceinline__ uint32_t packh(float lo, float hi) {
    uint32_t r;
    asm("cvt.rn.f16x2.f32 %0, %1, %2;" : "=r"(r) : "f"(hi), "f"(lo));
    return r;
}
__device__ __forceinline__ void cpa16(uint32_t dst, const void* src) {
    asm volatile("cp.async.cg.shared.global [%0], [%1], 16;" :: "r"(dst), "l"(src));
}
#define CP_COMMIT() asm volatile("cp.async.commit_group;" ::: "memory")
#define CP_WAIT1()  asm volatile("cp.async.wait_group 1;" ::: "memory")
#define CP_WAIT0()  asm volatile("cp.async.wait_group 0;" ::: "memory")

// ---------------- LayerNorm (fp32 out) ----------------
__global__ void ln_kernel(const float* __restrict__ x, const float* __restrict__ w,
                          const float* __restrict__ b, float* __restrict__ out) {
    const int row = blockIdx.x, t = threadIdx.x;
    const float4 v = ((const float4*)(x + (size_t)row * DIM))[t];
    float s = v.x + v.y + v.z + v.w;
    float sq = v.x*v.x + v.y*v.y + v.z*v.z + v.w*v.w;
    #pragma unroll
    for (int m = 16; m > 0; m >>= 1) {
        s += __shfl_xor_sync(~0u, s, m);  sq += __shfl_xor_sync(~0u, sq, m);
    }
    __shared__ float ss[8], ssq[8];
    const int wid = t >> 5, lane = t & 31;
    if (lane == 0) { ss[wid] = s; ssq[wid] = sq; }
    __syncthreads();
    if (wid == 0) {
        s = (lane < 8) ? ss[lane] : 0.f;  sq = (lane < 8) ? ssq[lane] : 0.f;
        #pragma unroll
        for (int m = 4; m > 0; m >>= 1) {
            s += __shfl_xor_sync(~0u, s, m);  sq += __shfl_xor_sync(~0u, sq, m);
        }
        if (lane == 0) { ss[0] = s; ssq[0] = sq; }
    }
    __syncthreads();
    const float mu = ss[0] * (1.0f / DIM);
    const float rstd = rsqrtf(ssq[0] * (1.0f / DIM) - mu * mu + 1e-5f);
    const float4 wv = ((const float4*)w)[t];
    const float4 bv = ((const float4*)b)[t];
    float4 o;
    o.x = (v.x - mu) * rstd * wv.x + bv.x;  o.y = (v.y - mu) * rstd * wv.y + bv.y;
    o.z = (v.z - mu) * rstd * wv.z + bv.z;  o.w = (v.w - mu) * rstd * wv.w + bv.w;
    ((float4*)(out + (size_t)row * DIM))[t] = o;
}

// ---------------- LayerNorm -> split bf16 ----------------
__global__ void ln_split_kernel(const float* __restrict__ x, const float* __restrict__ w,
                                const float* __restrict__ b,
                                bf16* __restrict__ oh, bf16* __restrict__ ol) {
    const int row = blockIdx.x, t = threadIdx.x;
    const float4 v = ((const float4*)(x + (size_t)row * DIM))[t];
    float s = v.x + v.y + v.z + v.w;
    float sq = v.x*v.x + v.y*v.y + v.z*v.z + v.w*v.w;
    #pragma unroll
    for (int m = 16; m > 0; m >>= 1) {
        s += __shfl_xor_sync(~0u, s, m);  sq += __shfl_xor_sync(~0u, sq, m);
    }
    __shared__ float ss[8], ssq[8];
    const int wid = t >> 5, lane = t & 31;
    if (lane == 0) { ss[wid] = s; ssq[wid] = sq; }
    __syncthreads();
    if (wid == 0) {
        s = (lane < 8) ? ss[lane] : 0.f;  sq = (lane < 8) ? ssq[lane] : 0.f;
        #pragma unroll
        for (int m = 4; m > 0; m >>= 1) {
            s += __shfl_xor_sync(~0u, s, m);  sq += __shfl_xor_sync(~0u, sq, m);
        }
        if (lane == 0) { ss[0] = s; ssq[0] = sq; }
    }
    __syncthreads();
    const float mu = ss[0] * (1.0f / DIM);
    const float rstd = rsqrtf(ssq[0] * (1.0f / DIM) - mu * mu + 1e-5f);
    const float4 wv = ((const float4*)w)[t];
    const float4 bv = ((const float4*)b)[t];
    float o[4];
    o[0] = (v.x - mu) * rstd * wv.x + bv.x;  o[1] = (v.y - mu) * rstd * wv.y + bv.y;
    o[2] = (v.z - mu) * rstd * wv.z + bv.z;  o[3] = (v.w - mu) * rstd * wv.w + bv.w;
    size_t base = (size_t)row * DIM + t * 4;
    #pragma unroll
    for (int j = 0; j < 4; j += 2) {
        bf16 h0 = __float2bfloat16(o[j]),     h1 = __float2bfloat16(o[j + 1]);
        bf16 l0 = __float2bfloat16(o[j] - __bfloat162float(h0));
        bf16 l1 = __float2bfloat16(o[j + 1] - __bfloat162float(h1));
        *(__nv_bfloat162*)(oh + base + j) = __halves2bfloat162(h0, h1);
        *(__nv_bfloat162*)(ol + base + j) = __halves2bfloat162(l0, l1);
    }
}

// ---------------- weight transpose + split (+scale) ----------------
__global__ void wtrans_kernel(const float* __restrict__ W, bf16* __restrict__ Th,
                              bf16* __restrict__ Tl, int K, int N, float scale) {
    __shared__ float tile[32][33];
    const int n0 = blockIdx.x * 32, k0 = blockIdx.y * 32;
    const int tx = threadIdx.x, ty = threadIdx.y;   // 32x8
    #pragma unroll
    for (int j = 0; j < 4; j++)
        tile[ty + 8 * j][tx] = W[(size_t)(k0 + ty + 8 * j) * N + n0 + tx];
    __syncthreads();
    #pragma unroll
    for (int j = 0; j < 4; j++) {
        float v = tile[tx][ty + 8 * j] * scale;
        bf16 h = __float2bfloat16(v);
        bf16 l = __float2bfloat16(v - __bfloat162float(h));
        size_t idx = (size_t)(n0 + ty + 8 * j) * K + k0 + tx;
        Th[idx] = h;  Tl[idx] = l;
    }
}

// ---------------- QKV post-convert: fp32 -> Q split bf16, K split bf16, V fp16 ----------------
__global__ void qkv_convert(const float* __restrict__ qkv,
                            bf16* __restrict__ qh, bf16* __restrict__ ql,
                            bf16* __restrict__ kh, bf16* __restrict__ kl,
                            __half* __restrict__ vh) {
    size_t idx = (size_t)blockIdx.x * 256 + threadIdx.x;   // MROWS*160 total
    int row = (int)(idx / 160), c = (int)(idx % 160) * 4;
    float4 v = *(const float4*)(qkv + (size_t)row * NQKV + c);
    float vv[4] = {v.x, v.y, v.z, v.w};
    if (c < 512) {
        size_t o = (size_t)row * INNER + c;
        #pragma unroll
        for (int j = 0; j < 4; j += 2) {
            bf16 h0 = __float2bfloat16(vv[j]), h1 = __float2bfloat16(vv[j + 1]);
            bf16 l0 = __float2bfloat16(vv[j] - __bfloat162float(h0));
            bf16 l1 = __float2bfloat16(vv[j + 1] - __bfloat162float(h1));
            *(__nv_bfloat162*)(qh + o + j) = __halves2bfloat162(h0, h1);
            *(__nv_bfloat162*)(ql + o + j) = __halves2bfloat162(l0, l1);
        }
    } else if (c < 576) {
        size_t o = (size_t)row * DHEAD + (c - 512);
        #pragma unroll
        for (int j = 0; j < 4; j += 2) {
            bf16 h0 = __float2bfloat16(vv[j]), h1 = __float2bfloat16(vv[j + 1]);
            bf16 l0 = __float2bfloat16(vv[j] - __bfloat162float(h0));
            bf16 l1 = __float2bfloat16(vv[j + 1] - __bfloat162float(h1));
            *(__nv_bfloat162*)(kh + o + j) = __halves2bfloat162(h0, h1);
            *(__nv_bfloat162*)(kl + o + j) = __halves2bfloat162(l0, l1);
        }
    } else {
        size_t o = (size_t)row * DHEAD + (c - 576);
        *(__half2*)(vh + o)     = __floats2half2_rn(vv[0], vv[1]);
        *(__half2*)(vh + o + 2) = __floats2half2_rn(vv[2], vv[3]);
    }
}

// ---------------- HMMA split-bf16 GEMM with cp.async double buffer ----------------
// C[M,N] = A @ B^T.  A hi/lo [M][K], B hi/lo [N][K].  Tile 128x128x64.
#define GP 72                       // padded smem row (bf16 elems), 144 B
#define GARR  (128 * GP * 2)        // 18432 B per matrix
#define GSTG  (4 * GARR)            // 73728 B per stage
#define GEMM_SMEM (2 * GSTG)        // 147456 B

__global__ __launch_bounds__(256, 1)
void gemm_hmma(const bf16* __restrict__ Ah, const bf16* __restrict__ Al,
               const bf16* __restrict__ Bh, const bf16* __restrict__ Bl,
               float* __restrict__ C, int N, int K) {
    extern __shared__ char sm[];
    const int tid = threadIdx.x, lane = tid & 31, wid = tid >> 5;
    const int wm = wid >> 1, wn = wid & 1;
    const int bm = blockIdx.y * 128, bn = blockIdx.x * 128;
    const uint32_t sb = smem_u32(sm);

    const bf16* src[4] = {Ah, Al, Bh, Bl};
    const int   r0 [4] = {bm, bm, bn, bn};

    auto load_stage = [&](int st, int k0) {
        uint32_t base = sb + (uint32_t)st * GSTG;
        #pragma unroll
        for (int j = 0; j < 16; j++) {
            int arr = j >> 2;
            int within = tid + (j & 3) * 256 + 0;          // 0..1023 per array
            int r = within >> 3, ch = within & 7;
            cpa16(base + arr * GARR + r * 144 + ch * 16,
                  src[arr] + (size_t)(r0[arr] + r) * K + k0 + ch * 8);
        }
    };

    float d[2][8][4] = {};
    const int a_r = wm * 32 + (lane & 15), a_c = (lane >> 4) * 8;
    const int b_r = wn * 64 + (lane >> 4) * 8 + (lane & 7), b_c = ((lane >> 3) & 1) * 8;

    const int T = K / 64;
    load_stage(0, 0);
    CP_COMMIT();

    for (int it = 0; it < T; it++) {
        if (it + 1 < T) { load_stage((it + 1) & 1, (it + 1) * 64); CP_COMMIT(); CP_WAIT1(); }
        else            { CP_WAIT0(); }
        __syncthreads();

        const uint32_t stg = sb + (uint32_t)(it & 1) * GSTG;
        #pragma unroll
        for (int ks = 0; ks < 4; ks++) {
            uint32_t aH[2][4], aL[2][4];
            #pragma unroll
            for (int mi = 0; mi < 2; mi++) {
                uint32_t off = (uint32_t)((a_r + mi * 16) * GP + ks * 16 + a_c) * 2;
                ldsm4(aH[mi], stg + 0 * GARR + off);
                ldsm4(aL[mi], stg + 1 * GARR + off);
            }
            #pragma unroll
            for (int jp = 0; jp < 4; jp++) {
                uint32_t bH[4], bL[4];
                uint32_t off = (uint32_t)((jp * 16 + b_r) * GP + ks * 16 + b_c) * 2;
                ldsm4(bH, stg + 2 * GARR + off);
                ldsm4(bL, stg + 3 * GARR + off);
                #pragma unroll
                for (int mi = 0; mi < 2; mi++) {
                    mma16816(d[mi][2 * jp],     aH[mi], bH);
                    mma16816(d[mi][2 * jp],     aH[mi], bL);
                    mma16816(d[mi][2 * jp],     aL[mi], bH);
                    mma16816(d[mi][2 * jp + 1], aH[mi], bH + 2);
                    mma16816(d[mi][2 * jp + 1], aH[mi], bL + 2);
                    mma16816(d[mi][2 * jp + 1], aL[mi], bH + 2);
                }
            }
        }
        __syncthreads();
    }

    #pragma unroll
    for (int mi = 0; mi < 2; mi++) {
        int row = bm + wm * 32 + mi * 16 + (lane >> 2);
        #pragma unroll
        for (int jt = 0; jt < 8; jt++) {
            int col = bn + wn * 64 + jt * 8 + (lane & 3) * 2;
            *(float2*)(C + (size_t)row * N + col)       = make_float2(d[mi][jt][0], d[mi][jt][1]);
            *(float2*)(C + (size_t)(row + 8) * N + col) = make_float2(d[mi][jt][2], d[mi][jt][3]);
        }
    }
}

// ---------------- HMMA flash attention, pre-split inputs + cp.async ----------------
// grid (SEQ/128, BATCH*HEADS), 256 threads (8 warps x 16 q-rows).
// smem bytes: QH 0, QL 18432, stages at 36864 + s*27648 (KH 0, KL 9216, VB 18432)
#define AQ    18432
#define ASTG0 36864
#define ASTG  27648
#define AKARR 9216
#define ATTN_SMEM (ASTG0 + 2 * ASTG)   // 92160

__global__ __launch_bounds__(256, 2)
void attn_hmma(const bf16* __restrict__ Qh, const bf16* __restrict__ Ql,
               const bf16* __restrict__ Kh, const bf16* __restrict__ Kl,
               const __half* __restrict__ Vh,
               bf16* __restrict__ Oh, bf16* __restrict__ Ol) {
    extern __shared__ char sm[];
    const int tid = threadIdx.x, lane = tid & 31, wid = tid >> 5;
    const int qt = blockIdx.x, bh = blockIdx.y;
    const int b = bh >> 3, h = bh & 7;
    const int qrow0 = b * SEQ + qt * 128;
    const int krow0 = b * SEQ;
    const uint32_t sb = smem_u32(sm);

    // load Q tile (128 x 64 split bf16) straight into padded smem
    #pragma unroll
    for (int j = 0; j < 8; j++) {
        int within = (tid + (j & 3) * 256);          // 0..1023
        int r = within >> 3, ch = within & 7;
        const bf16* srcp = (j < 4) ? Qh : Ql;
        uint32_t dst = sb + ((j < 4) ? 0 : AQ) + r * 144 + ch * 16;
        *(uint4*)(sm + (dst - sb)) =
            *(const uint4*)(srcp + (size_t)(qrow0 + r) * INNER + h * DHEAD + ch * 8);
    }

    auto load_kv = [&](int st, int kt) {
        uint32_t base = sb + ASTG0 + (uint32_t)st * ASTG;
        int krow = krow0 + kt * 64;
        #pragma unroll
        for (int j = 0; j < 6; j++) {
            int within = tid + (j & 1) * 256;        // 0..511 per array
            int arr = j >> 1;
            int r = within >> 3, ch = within & 7;
            const void* srcp;
            if      (arr == 0) srcp = Kh + (size_t)(krow + r) * DHEAD + ch * 8;
            else if (arr == 1) srcp = Kl + (size_t)(krow + r) * DHEAD + ch * 8;
            else               srcp = Vh + (size_t)(krow + r) * DHEAD + ch * 8;
            cpa16(base + arr * AKARR + r * 144 + ch * 16, srcp);
        }
    };

    const int rbase = wid * 16;
    const int a_r = rbase + (lane & 15), a_c = (lane >> 4) * 8;
    const int b_r = (lane >> 4) * 8 + (lane & 7), b_c = ((lane >> 3) & 1) * 8;
    const int v_r = ((lane >> 3) & 1) * 8 + (lane & 7), v_c = (lane >> 4) * 8;

    float o[8][4] = {};
    float mreg[2] = {-1e30f, -1e30f}, lreg[2] = {0.f, 0.f};

    const int T = SEQ / 64;
    load_kv(0, 0);
    CP_COMMIT();

    for (int kt = 0; kt < T; kt++) {
        if (kt + 1 < T) { load_kv((kt + 1) & 1, kt + 1); CP_COMMIT(); CP_WAIT1(); }
        else            { CP_WAIT0(); }
        __syncthreads();

        const uint32_t stg = sb + ASTG0 + (uint32_t)(kt & 1) * ASTG;

        // S = Q @ K^T (split-bf16, 3 products)
        float s[8][4] = {};
        #pragma unroll
        for (int dk = 0; dk < 4; dk++) {
            uint32_t aH[4], aL[4];
            uint32_t aoff = (uint32_t)(a_r * GP + dk * 16 + a_c) * 2;
            ldsm4(aH, sb + 0  + aoff);
            ldsm4(aL, sb + AQ + aoff);
            #pragma unroll
            for (int jp = 0; jp < 4; jp++) {
                uint32_t bH[4], bL[4];
                uint32_t koff = (uint32_t)((jp * 16 + b_r) * GP + dk * 16 + b_c) * 2;
                ldsm4(bH, stg + 0 * AKARR + koff);
                ldsm4(bL, stg + 1 * AKARR + koff);
                mma16816(s[2 * jp],     aH, bH);
                mma16816(s[2 * jp],     aH, bL);
                mma16816(s[2 * jp],     aL, bH);
                mma16816(s[2 * jp + 1], aH, bH + 2);
                mma16816(s[2 * jp + 1], aH, bL + 2);
                mma16816(s[2 * jp + 1], aL, bH + 2);
            }
        }

        // online softmax
        #pragma unroll
        for (int e = 0; e < 2; e++) {
            float rmax = -1e30f;
            #pragma unroll
            for (int jt = 0; jt < 8; jt++)
                rmax = fmaxf(rmax, fmaxf(s[jt][2 * e], s[jt][2 * e + 1]));
            rmax = fmaxf(rmax, __shfl_xor_sync(~0u, rmax, 1));
            rmax = fmaxf(rmax, __shfl_xor_sync(~0u, rmax, 2));
            float mn = fmaxf(mreg[e], rmax);
            float corr = __expf(mreg[e] - mn);
            mreg[e] = mn;
            float rsum = 0.f;
            #pragma unroll
            for (int jt = 0; jt < 8; jt++) {
                s[jt][2 * e]     = __expf(s[jt][2 * e] - mn);
                s[jt][2 * e + 1] = __expf(s[jt][2 * e + 1] - mn);
                rsum += s[jt][2 * e] + s[jt][2 * e + 1];
            }
            rsum += __shfl_xor_sync(~0u, rsum, 1);
            rsum += __shfl_xor_sync(~0u, rsum, 2);
            lreg[e] = lreg[e] * corr + rsum;
            #pragma unroll
            for (int jt = 0; jt < 8; jt++) { o[jt][2 * e] *= corr; o[jt][2 * e + 1] *= corr; }
        }

        // O += P @ V  (fp16)
        #pragma unroll
        for (int kk = 0; kk < 4; kk++) {
            uint32_t aP[4] = {
                packh(s[2 * kk][0],     s[2 * kk][1]),
                packh(s[2 * kk][2],     s[2 * kk][3]),
                packh(s[2 * kk + 1][0], s[2 * kk + 1][1]),
                packh(s[2 * kk + 1][2], s[2 * kk + 1][3])
            };
            #pragma unroll
            for (int dp = 0; dp < 4; dp++) {
                uint32_t bV[4];
                ldsm4t(bV, stg + 2 * AKARR + (uint32_t)((kk * 16 + v_r) * GP + dp * 16 + v_c) * 2);
                mma16816h(o[2 * dp],     aP, bV);
                mma16816h(o[2 * dp + 1], aP, bV + 2);
            }
        }
        __syncthreads();
    }

    // epilogue: normalize, split-bf16 store
    #pragma unroll
    for (int e = 0; e < 2; e++) {
        float inv = 1.0f / lreg[e];
        int row = qrow0 + rbase + (lane >> 2) + 8 * e;
        #pragma unroll
        for (int dd = 0; dd < 8; dd++) {
            float v0 = o[dd][2 * e] * inv, v1 = o[dd][2 * e + 1] * inv;
            bf16 h0 = __float2bfloat16(v0), h1 = __float2bfloat16(v1);
            bf16 l0 = __float2bfloat16(v0 - __bfloat162float(h0));
            bf16 l1 = __float2bfloat16(v1 - __bfloat162float(h1));
            size_t base = (size_t)row * INNER + h * DHEAD + dd * 8 + (lane & 3) * 2;
            *(__nv_bfloat162*)(Oh + base) = __halves2bfloat162(h0, h1);
            *(__nv_bfloat162*)(Ol + base) = __halves2bfloat162(l0, l1);
        }
    }
}

// ---------------- launch ----------------
extern "C" void kernel_launch(void* const* d_in, const int* in_sizes, int n_in,
                              void* d_out, int out_size) {
    const float* x   = (const float*)d_in[0];
    const float* Wq  = (const float*)d_in[1];
    const float* Wkv = (const float*)d_in[2];
    const float* Wo  = (const float*)d_in[3];
    const float* nw  = (const float*)d_in[4];
    const float* nb  = (const float*)d_in[5];
    const float* onw = (const float*)d_in[6];
    const float* onb = (const float*)d_in[7];
    float* out = (float*)d_out;

    bf16 *xnh, *xnl, *qh, *ql, *kh, *kl, *atth, *attl, *w1h, *w1l, *woh, *wol;
    __half* vh;
    float *qkv, *proj;
    cudaGetSymbolAddress((void**)&xnh,  g_xnh);
    cudaGetSymbolAddress((void**)&xnl,  g_xnl);
    cudaGetSymbolAddress((void**)&qkv,  g_qkv);
    cudaGetSymbolAddress((void**)&qh,   g_qh);
    cudaGetSymbolAddress((void**)&ql,   g_ql);
    cudaGetSymbolAddress((void**)&kh,   g_kh);
    cudaGetSymbolAddress((void**)&kl,   g_kl);
    cudaGetSymbolAddress((void**)&vh,   g_vh);
    cudaGetSymbolAddress((void**)&atth, g_atth);
    cudaGetSymbolAddress((void**)&attl, g_attl);
    cudaGetSymbolAddress((void**)&proj, g_proj);
    cudaGetSymbolAddress((void**)&w1h,  g_w1h);
    cudaGetSymbolAddress((void**)&w1l,  g_w1l);
    cudaGetSymbolAddress((void**)&woh,  g_woh);
    cudaGetSymbolAddress((void**)&wol,  g_wol);

    cudaFuncSetAttribute(gemm_hmma, cudaFuncAttributeMaxDynamicSharedMemorySize, GEMM_SMEM);
    cudaFuncSetAttribute(attn_hmma, cudaFuncAttributeMaxDynamicSharedMemorySize, ATTN_SMEM);

    // weight transpose + split (+fold QK scale into Wq)
    wtrans_kernel<<<dim3(INNER / 32, DIM / 32), dim3(32, 8)>>>(Wq, w1h, w1l, DIM, INNER, QK_SCALE);
    wtrans_kernel<<<dim3(128 / 32, DIM / 32), dim3(32, 8)>>>(Wkv, w1h + (size_t)512 * DIM,
                                                             w1l + (size_t)512 * DIM, DIM, 128, 1.0f);
    wtrans_kernel<<<dim3(DIM / 32, INNER / 32), dim3(32, 8)>>>(Wo, woh, wol, INNER, DIM, 1.0f);

    // 1) pre-LN -> split bf16
    ln_split_kernel<<<MROWS, 256>>>(x, nw, nb, xnh, xnl);
    // 2) merged QKV GEMM
    gemm_hmma<<<dim3(NQKV / 128, MROWS / 128), 256, GEMM_SMEM>>>(xnh, xnl, w1h, w1l, qkv, NQKV, DIM);
    // 2b) convert QKV once: Q split bf16, K split bf16, V fp16
    qkv_convert<<<MROWS * 160 / 256, 256>>>(qkv, qh, ql, kh, kl, vh);
    // 3) flash attention
    attn_hmma<<<dim3(SEQ / 128, BATCH * HEADS), 256, ATTN_SMEM>>>(qh, ql, kh, kl, vh, atth, attl);
    // 4) out-projection
    gemm_hmma<<<dim3(DIM / 128, MROWS / 128), 256, GEMM_SMEM>>>(atth, attl, woh, wol, proj, DIM, INNER);
    // 5) post-LN
    ln_kernel<<<MROWS, 256>>>(proj, onw, onb, out);
}

// round 6
// speedup vs baseline: 4.7946x; 1.2075x over previous
#include <cuda_runtime.h>
#include <cuda_bf16.h>
#include <cuda_fp16.h>
#include <cstdint>

#define BATCH 4
#define SEQ   2048
#define DIM   1024
#define HEADS 8
#define DHEAD 64
#define INNER 512
#define MROWS 8192
#define NQKV  640            // 512 (Q) + 64 (K) + 64 (V)
#define QK_SCALE 0.125f

typedef __nv_bfloat16 bf16;

// ---------------- scratch ----------------
__device__ bf16   g_xnh [MROWS * DIM];
__device__ bf16   g_xnl [MROWS * DIM];
__device__ __half g_q16 [MROWS * INNER];
__device__ __half g_k16 [MROWS * DHEAD];
__device__ __half g_v16 [MROWS * DHEAD];
__device__ bf16   g_atth[MROWS * INNER];
__device__ bf16   g_attl[MROWS * INNER];
__device__ float  g_proj[MROWS * DIM];
__device__ bf16   g_w1h [NQKV * DIM], g_w1l [NQKV * DIM];   // [n][k]: Wq^T*s | Wkv^T
__device__ bf16   g_woh [DIM * INNER], g_wol [DIM * INNER]; // [n][k]

// ---------------- helpers ----------------
__device__ __forceinline__ uint32_t smem_u32(const void* p) {
    uint32_t a;
    asm("{ .reg .u64 t; cvta.to.shared.u64 t, %1; cvt.u32.u64 %0, t; }" : "=r"(a) : "l"(p));
    return a;
}
__device__ __forceinline__ void ldsm4(uint32_t* r, uint32_t a) {
    asm volatile("ldmatrix.sync.aligned.m8n8.x4.shared.b16 {%0,%1,%2,%3}, [%4];"
                 : "=r"(r[0]), "=r"(r[1]), "=r"(r[2]), "=r"(r[3]) : "r"(a));
}
__device__ __forceinline__ void ldsm4t(uint32_t* r, uint32_t a) {
    asm volatile("ldmatrix.sync.aligned.m8n8.x4.trans.shared.b16 {%0,%1,%2,%3}, [%4];"
                 : "=r"(r[0]), "=r"(r[1]), "=r"(r[2]), "=r"(r[3]) : "r"(a));
}
__device__ __forceinline__ void mma16816(float* d, const uint32_t* a, const uint32_t* b) {
    asm volatile(
        "mma.sync.aligned.m16n8k16.row.col.f32.bf16.bf16.f32 "
        "{%0,%1,%2,%3}, {%4,%5,%6,%7}, {%8,%9}, {%0,%1,%2,%3};"
        : "+f"(d[0]), "+f"(d[1]), "+f"(d[2]), "+f"(d[3])
        : "r"(a[0]), "r"(a[1]), "r"(a[2]), "r"(a[3]), "r"(b[0]), "r"(b[1]));
}
__device__ __forceinline__ void mma16816h(float* d, const uint32_t* a, const uint32_t* b) {
    asm volatile(
        "mma.sync.aligned.m16n8k16.row.col.f32.f16.f16.f32 "
        "{%0,%1,%2,%3}, {%4,%5,%6,%7}, {%8,%9}, {%0,%1,%2,%3};"
        : "+f"(d[0]), "+f"(d[1]), "+f"(d[2]), "+f"(d[3])
        : "r"(a[0]), "r"(a[1]), "r"(a[2]), "r"(a[3]), "r"(b[0]), "r"(b[1]));
}
__device__ __forceinline__ uint32_t packh(float lo, float hi) {
    uint32_t r;
    asm("cvt.rn.f16x2.f32 %0, %1, %2;" : "=r"(r) : "f"(hi), "f"(lo));
    return r;
}
__device__ __forceinline__ void cpa16(uint32_t dst, const void* src) {
    asm volatile("cp.async.cg.shared.global [%0], [%1], 16;" :: "r"(dst), "l"(src));
}
#define CP_COMMIT() asm volatile("cp.async.commit_group;" ::: "memory")
#define CP_WAIT1()  asm volatile("cp.async.wait_group 1;" ::: "memory")
#define CP_WAIT0()  asm volatile("cp.async.wait_group 0;" ::: "memory")

// ---------------- LayerNorm (fp32 out) ----------------
__global__ void ln_kernel(const float* __restrict__ x, const float* __restrict__ w,
                          const float* __restrict__ b, float* __restrict__ out) {
    const int row = blockIdx.x, t = threadIdx.x;
    const float4 v = ((const float4*)(x + (size_t)row * DIM))[t];
    float s = v.x + v.y + v.z + v.w;
    float sq = v.x*v.x + v.y*v.y + v.z*v.z + v.w*v.w;
    #pragma unroll
    for (int m = 16; m > 0; m >>= 1) {
        s += __shfl_xor_sync(~0u, s, m);  sq += __shfl_xor_sync(~0u, sq, m);
    }
    __shared__ float ss[8], ssq[8];
    const int wid = t >> 5, lane = t & 31;
    if (lane == 0) { ss[wid] = s; ssq[wid] = sq; }
    __syncthreads();
    if (wid == 0) {
        s = (lane < 8) ? ss[lane] : 0.f;  sq = (lane < 8) ? ssq[lane] : 0.f;
        #pragma unroll
        for (int m = 4; m > 0; m >>= 1) {
            s += __shfl_xor_sync(~0u, s, m);  sq += __shfl_xor_sync(~0u, sq, m);
        }
        if (lane == 0) { ss[0] = s; ssq[0] = sq; }
    }
    __syncthreads();
    const float mu = ss[0] * (1.0f / DIM);
    const float rstd = rsqrtf(ssq[0] * (1.0f / DIM) - mu * mu + 1e-5f);
    const float4 wv = ((const float4*)w)[t];
    const float4 bv = ((const float4*)b)[t];
    float4 o;
    o.x = (v.x - mu) * rstd * wv.x + bv.x;  o.y = (v.y - mu) * rstd * wv.y + bv.y;
    o.z = (v.z - mu) * rstd * wv.z + bv.z;  o.w = (v.w - mu) * rstd * wv.w + bv.w;
    ((float4*)(out + (size_t)row * DIM))[t] = o;
}

// ---------------- LayerNorm -> split bf16 ----------------
__global__ void ln_split_kernel(const float* __restrict__ x, const float* __restrict__ w,
                                const float* __restrict__ b,
                                bf16* __restrict__ oh, bf16* __restrict__ ol) {
    const int row = blockIdx.x, t = threadIdx.x;
    const float4 v = ((const float4*)(x + (size_t)row * DIM))[t];
    float s = v.x + v.y + v.z + v.w;
    float sq = v.x*v.x + v.y*v.y + v.z*v.z + v.w*v.w;
    #pragma unroll
    for (int m = 16; m > 0; m >>= 1) {
        s += __shfl_xor_sync(~0u, s, m);  sq += __shfl_xor_sync(~0u, sq, m);
    }
    __shared__ float ss[8], ssq[8];
    const int wid = t >> 5, lane = t & 31;
    if (lane == 0) { ss[wid] = s; ssq[wid] = sq; }
    __syncthreads();
    if (wid == 0) {
        s = (lane < 8) ? ss[lane] : 0.f;  sq = (lane < 8) ? ssq[lane] : 0.f;
        #pragma unroll
        for (int m = 4; m > 0; m >>= 1) {
            s += __shfl_xor_sync(~0u, s, m);  sq += __shfl_xor_sync(~0u, sq, m);
        }
        if (lane == 0) { ss[0] = s; ssq[0] = sq; }
    }
    __syncthreads();
    const float mu = ss[0] * (1.0f / DIM);
    const float rstd = rsqrtf(ssq[0] * (1.0f / DIM) - mu * mu + 1e-5f);
    const float4 wv = ((const float4*)w)[t];
    const float4 bv = ((const float4*)b)[t];
    float o[4];
    o[0] = (v.x - mu) * rstd * wv.x + bv.x;  o[1] = (v.y - mu) * rstd * wv.y + bv.y;
    o[2] = (v.z - mu) * rstd * wv.z + bv.z;  o[3] = (v.w - mu) * rstd * wv.w + bv.w;
    size_t base = (size_t)row * DIM + t * 4;
    #pragma unroll
    for (int j = 0; j < 4; j += 2) {
        bf16 h0 = __float2bfloat16(o[j]),     h1 = __float2bfloat16(o[j + 1]);
        bf16 l0 = __float2bfloat16(o[j] - __bfloat162float(h0));
        bf16 l1 = __float2bfloat16(o[j + 1] - __bfloat162float(h1));
        *(__nv_bfloat162*)(oh + base + j) = __halves2bfloat162(h0, h1);
        *(__nv_bfloat162*)(ol + base + j) = __halves2bfloat162(l0, l1);
    }
}

// ---------------- weight transpose + split (+scale) ----------------
__global__ void wtrans_kernel(const float* __restrict__ W, bf16* __restrict__ Th,
                              bf16* __restrict__ Tl, int K, int N, float scale) {
    __shared__ float tile[32][33];
    const int n0 = blockIdx.x * 32, k0 = blockIdx.y * 32;
    const int tx = threadIdx.x, ty = threadIdx.y;   // 32x8
    #pragma unroll
    for (int j = 0; j < 4; j++)
        tile[ty + 8 * j][tx] = W[(size_t)(k0 + ty + 8 * j) * N + n0 + tx];
    __syncthreads();
    #pragma unroll
    for (int j = 0; j < 4; j++) {
        float v = tile[tx][ty + 8 * j] * scale;
        bf16 h = __float2bfloat16(v);
        bf16 l = __float2bfloat16(v - __bfloat162float(h));
        size_t idx = (size_t)(n0 + ty + 8 * j) * K + k0 + tx;
        Th[idx] = h;  Tl[idx] = l;
    }
}

// ---------------- HMMA split-bf16 GEMM with cp.async double buffer ----------------
// C[M,N] = A @ B^T.  MODE 0: fp32 C.  MODE 1: fp16 scatter to Q/K/V buffers.
#define GP 72                       // padded smem row (bf16 elems), 144 B
#define GARR  (128 * GP * 2)        // 18432 B per matrix
#define GSTG  (4 * GARR)            // 73728 B per stage
#define GEMM_SMEM (2 * GSTG)        // 147456 B

template<int MODE>
__global__ __launch_bounds__(256, 1)
void gemm_hmma(const bf16* __restrict__ Ah, const bf16* __restrict__ Al,
               const bf16* __restrict__ Bh, const bf16* __restrict__ Bl,
               float* __restrict__ C,
               __half* __restrict__ q16, __half* __restrict__ k16, __half* __restrict__ v16,
               int N, int K) {
    extern __shared__ char sm[];
    const int tid = threadIdx.x, lane = tid & 31, wid = tid >> 5;
    const int wm = wid >> 1, wn = wid & 1;
    const int bm = blockIdx.y * 128, bn = blockIdx.x * 128;
    const uint32_t sb = smem_u32(sm);

    const bf16* src[4] = {Ah, Al, Bh, Bl};
    const int   r0 [4] = {bm, bm, bn, bn};

    auto load_stage = [&](int st, int k0) {
        uint32_t base = sb + (uint32_t)st * GSTG;
        #pragma unroll
        for (int j = 0; j < 16; j++) {
            int arr = j >> 2;
            int within = tid + (j & 3) * 256;
            int r = within >> 3, ch = within & 7;
            cpa16(base + arr * GARR + r * 144 + ch * 16,
                  src[arr] + (size_t)(r0[arr] + r) * K + k0 + ch * 8);
        }
    };

    float d[2][8][4] = {};
    const int a_r = wm * 32 + (lane & 15), a_c = (lane >> 4) * 8;
    const int b_r = wn * 64 + (lane >> 4) * 8 + (lane & 7), b_c = ((lane >> 3) & 1) * 8;

    const int T = K / 64;
    load_stage(0, 0);
    CP_COMMIT();

    for (int it = 0; it < T; it++) {
        if (it + 1 < T) { load_stage((it + 1) & 1, (it + 1) * 64); CP_COMMIT(); CP_WAIT1(); }
        else            { CP_WAIT0(); }
        __syncthreads();

        const uint32_t stg = sb + (uint32_t)(it & 1) * GSTG;
        #pragma unroll
        for (int ks = 0; ks < 4; ks++) {
            uint32_t aH[2][4], aL[2][4];
            #pragma unroll
            for (int mi = 0; mi < 2; mi++) {
                uint32_t off = (uint32_t)((a_r + mi * 16) * GP + ks * 16 + a_c) * 2;
                ldsm4(aH[mi], stg + 0 * GARR + off);
                ldsm4(aL[mi], stg + 1 * GARR + off);
            }
            #pragma unroll
            for (int jp = 0; jp < 4; jp++) {
                uint32_t bH[4], bL[4];
                uint32_t off = (uint32_t)((jp * 16 + b_r) * GP + ks * 16 + b_c) * 2;
                ldsm4(bH, stg + 2 * GARR + off);
                ldsm4(bL, stg + 3 * GARR + off);
                #pragma unroll
                for (int mi = 0; mi < 2; mi++) {
                    mma16816(d[mi][2 * jp],     aH[mi], bH);
                    mma16816(d[mi][2 * jp],     aH[mi], bL);
                    mma16816(d[mi][2 * jp],     aL[mi], bH);
                    mma16816(d[mi][2 * jp + 1], aH[mi], bH + 2);
                    mma16816(d[mi][2 * jp + 1], aH[mi], bL + 2);
                    mma16816(d[mi][2 * jp + 1], aL[mi], bH + 2);
                }
            }
        }
        __syncthreads();
    }

    #pragma unroll
    for (int mi = 0; mi < 2; mi++) {
        int row = bm + wm * 32 + mi * 16 + (lane >> 2);
        #pragma unroll
        for (int jt = 0; jt < 8; jt++) {
            int col = bn + wn * 64 + jt * 8 + (lane & 3) * 2;
            if (MODE == 0) {
                *(float2*)(C + (size_t)row * N + col)       = make_float2(d[mi][jt][0], d[mi][jt][1]);
                *(float2*)(C + (size_t)(row + 8) * N + col) = make_float2(d[mi][jt][2], d[mi][jt][3]);
            } else {
                #pragma unroll
                for (int rr = 0; rr < 2; rr++) {
                    int r2 = row + rr * 8;
                    __half2 hv = __floats2half2_rn(d[mi][jt][2 * rr], d[mi][jt][2 * rr + 1]);
                    if (col < 512)      *(__half2*)(q16 + (size_t)r2 * INNER + col)        = hv;
                    else if (col < 576) *(__half2*)(k16 + (size_t)r2 * DHEAD + (col - 512)) = hv;
                    else                *(__half2*)(v16 + (size_t)r2 * DHEAD + (col - 576)) = hv;
                }
            }
        }
    }
}

// ---------------- HMMA flash attention: fp16 QK single-product, fp16 PV ----------------
// grid (SEQ/128, BATCH*HEADS), 256 threads (8 warps x 16 q-rows).
// smem bytes: Q 0 (18432), stages at 18432 + s*18432 (K +0, V +9216)
#define AQSZ  18432
#define AKV   9216
#define ASTG2 (2 * AKV)
#define ATTN_SMEM (AQSZ + 2 * ASTG2)   // 55296

__global__ __launch_bounds__(256, 2)
void attn_hmma(const __half* __restrict__ Q16, const __half* __restrict__ K16,
               const __half* __restrict__ V16,
               bf16* __restrict__ Oh, bf16* __restrict__ Ol) {
    extern __shared__ char sm[];
    const int tid = threadIdx.x, lane = tid & 31, wid = tid >> 5;
    const int qt = blockIdx.x, bh = blockIdx.y;
    const int b = bh >> 3, h = bh & 7;
    const int qrow0 = b * SEQ + qt * 128;
    const int krow0 = b * SEQ;
    const uint32_t sb = smem_u32(sm);

    // load Q tile (128 x 64 fp16) into padded smem
    #pragma unroll
    for (int j = 0; j < 4; j++) {
        int within = tid + j * 256;               // 0..1023
        int r = within >> 3, ch = within & 7;
        *(uint4*)(sm + r * 144 + ch * 16) =
            *(const uint4*)(Q16 + (size_t)(qrow0 + r) * INNER + h * DHEAD + ch * 8);
    }

    auto load_kv = [&](int st, int kt) {
        uint32_t base = sb + AQSZ + (uint32_t)st * ASTG2;
        int krow = krow0 + kt * 64;
        #pragma unroll
        for (int j = 0; j < 4; j++) {
            int arr = j >> 1;
            int within = tid + (j & 1) * 256;     // 0..511 per array
            int r = within >> 3, ch = within & 7;
            const __half* srcp = (arr == 0)
                ? (K16 + (size_t)(krow + r) * DHEAD + ch * 8)
                : (V16 + (size_t)(krow + r) * DHEAD + ch * 8);
            cpa16(base + arr * AKV + r * 144 + ch * 16, srcp);
        }
    };

    const int rbase = wid * 16;
    const int a_r = rbase + (lane & 15), a_c = (lane >> 4) * 8;
    const int b_r = (lane >> 4) * 8 + (lane & 7), b_c = ((lane >> 3) & 1) * 8;
    const int v_r = ((lane >> 3) & 1) * 8 + (lane & 7), v_c = (lane >> 4) * 8;

    float o[8][4] = {};
    float mreg[2] = {-1e30f, -1e30f}, lreg[2] = {0.f, 0.f};

    const int T = SEQ / 64;
    load_kv(0, 0);
    CP_COMMIT();

    for (int kt = 0; kt < T; kt++) {
        if (kt + 1 < T) { load_kv((kt + 1) & 1, kt + 1); CP_COMMIT(); CP_WAIT1(); }
        else            { CP_WAIT0(); }
        __syncthreads();

        const uint32_t stg = sb + AQSZ + (uint32_t)(kt & 1) * ASTG2;

        // S = Q @ K^T (single fp16 product)
        float s[8][4] = {};
        #pragma unroll
        for (int dk = 0; dk < 4; dk++) {
            uint32_t aQ[4];
            ldsm4(aQ, sb + (uint32_t)(a_r * GP + dk * 16 + a_c) * 2);
            #pragma unroll
            for (int jp = 0; jp < 4; jp++) {
                uint32_t bK[4];
                ldsm4(bK, stg + (uint32_t)((jp * 16 + b_r) * GP + dk * 16 + b_c) * 2);
                mma16816h(s[2 * jp],     aQ, bK);
                mma16816h(s[2 * jp + 1], aQ, bK + 2);
            }
        }

        // online softmax
        #pragma unroll
        for (int e = 0; e < 2; e++) {
            float rmax = -1e30f;
            #pragma unroll
            for (int jt = 0; jt < 8; jt++)
                rmax = fmaxf(rmax, fmaxf(s[jt][2 * e], s[jt][2 * e + 1]));
            rmax = fmaxf(rmax, __shfl_xor_sync(~0u, rmax, 1));
            rmax = fmaxf(rmax, __shfl_xor_sync(~0u, rmax, 2));
            float mn = fmaxf(mreg[e], rmax);
            float corr = __expf(mreg[e] - mn);
            mreg[e] = mn;
            float rsum = 0.f;
            #pragma unroll
            for (int jt = 0; jt < 8; jt++) {
                s[jt][2 * e]     = __expf(s[jt][2 * e] - mn);
                s[jt][2 * e + 1] = __expf(s[jt][2 * e + 1] - mn);
                rsum += s[jt][2 * e] + s[jt][2 * e + 1];
            }
            rsum += __shfl_xor_sync(~0u, rsum, 1);
            rsum += __shfl_xor_sync(~0u, rsum, 2);
            lreg[e] = lreg[e] * corr + rsum;
            #pragma unroll
            for (int jt = 0; jt < 8; jt++) { o[jt][2 * e] *= corr; o[jt][2 * e + 1] *= corr; }
        }

        // O += P @ V  (fp16)
        #pragma unroll
        for (int kk = 0; kk < 4; kk++) {
            uint32_t aP[4] = {
                packh(s[2 * kk][0],     s[2 * kk][1]),
                packh(s[2 * kk][2],     s[2 * kk][3]),
                packh(s[2 * kk + 1][0], s[2 * kk + 1][1]),
                packh(s[2 * kk + 1][2], s[2 * kk + 1][3])
            };
            #pragma unroll
            for (int dp = 0; dp < 4; dp++) {
                uint32_t bV[4];
                ldsm4t(bV, stg + AKV + (uint32_t)((kk * 16 + v_r) * GP + dp * 16 + v_c) * 2);
                mma16816h(o[2 * dp],     aP, bV);
                mma16816h(o[2 * dp + 1], aP, bV + 2);
            }
        }
        __syncthreads();
    }

    // epilogue: normalize, split-bf16 store
    #pragma unroll
    for (int e = 0; e < 2; e++) {
        float inv = 1.0f / lreg[e];
        int row = qrow0 + rbase + (lane >> 2) + 8 * e;
        #pragma unroll
        for (int dd = 0; dd < 8; dd++) {
            float v0 = o[dd][2 * e] * inv, v1 = o[dd][2 * e + 1] * inv;
            bf16 h0 = __float2bfloat16(v0), h1 = __float2bfloat16(v1);
            bf16 l0 = __float2bfloat16(v0 - __bfloat162float(h0));
            bf16 l1 = __float2bfloat16(v1 - __bfloat162float(h1));
            size_t base = (size_t)row * INNER + h * DHEAD + dd * 8 + (lane & 3) * 2;
            *(__nv_bfloat162*)(Oh + base) = __halves2bfloat162(h0, h1);
            *(__nv_bfloat162*)(Ol + base) = __halves2bfloat162(l0, l1);
        }
    }
}

// ---------------- launch ----------------
extern "C" void kernel_launch(void* const* d_in, const int* in_sizes, int n_in,
                              void* d_out, int out_size) {
    const float* x   = (const float*)d_in[0];
    const float* Wq  = (const float*)d_in[1];
    const float* Wkv = (const float*)d_in[2];
    const float* Wo  = (const float*)d_in[3];
    const float* nw  = (const float*)d_in[4];
    const float* nb  = (const float*)d_in[5];
    const float* onw = (const float*)d_in[6];
    const float* onb = (const float*)d_in[7];
    float* out = (float*)d_out;

    bf16 *xnh, *xnl, *atth, *attl, *w1h, *w1l, *woh, *wol;
    __half *q16, *k16, *v16;
    float *proj;
    cudaGetSymbolAddress((void**)&xnh,  g_xnh);
    cudaGetSymbolAddress((void**)&xnl,  g_xnl);
    cudaGetSymbolAddress((void**)&q16,  g_q16);
    cudaGetSymbolAddress((void**)&k16,  g_k16);
    cudaGetSymbolAddress((void**)&v16,  g_v16);
    cudaGetSymbolAddress((void**)&atth, g_atth);
    cudaGetSymbolAddress((void**)&attl, g_attl);
    cudaGetSymbolAddress((void**)&proj, g_proj);
    cudaGetSymbolAddress((void**)&w1h,  g_w1h);
    cudaGetSymbolAddress((void**)&w1l,  g_w1l);
    cudaGetSymbolAddress((void**)&woh,  g_woh);
    cudaGetSymbolAddress((void**)&wol,  g_wol);

    cudaFuncSetAttribute(gemm_hmma<0>, cudaFuncAttributeMaxDynamicSharedMemorySize, GEMM_SMEM);
    cudaFuncSetAttribute(gemm_hmma<1>, cudaFuncAttributeMaxDynamicSharedMemorySize, GEMM_SMEM);
    cudaFuncSetAttribute(attn_hmma,    cudaFuncAttributeMaxDynamicSharedMemorySize, ATTN_SMEM);

    // weight transpose + split (+fold QK scale into Wq)
    wtrans_kernel<<<dim3(INNER / 32, DIM / 32), dim3(32, 8)>>>(Wq, w1h, w1l, DIM, INNER, QK_SCALE);
    wtrans_kernel<<<dim3(128 / 32, DIM / 32), dim3(32, 8)>>>(Wkv, w1h + (size_t)512 * DIM,
                                                             w1l + (size_t)512 * DIM, DIM, 128, 1.0f);
    wtrans_kernel<<<dim3(DIM / 32, INNER / 32), dim3(32, 8)>>>(Wo, woh, wol, INNER, DIM, 1.0f);

    // 1) pre-LN -> split bf16
    ln_split_kernel<<<MROWS, 256>>>(x, nw, nb, xnh, xnl);
    // 2) merged QKV GEMM with fused fp16 Q/K/V epilogue
    gemm_hmma<1><<<dim3(NQKV / 128, MROWS / 128), 256, GEMM_SMEM>>>(
        xnh, xnl, w1h, w1l, nullptr, q16, k16, v16, NQKV, DIM);
    // 3) flash attention (fp16 QK single product, fp16 PV)
    attn_hmma<<<dim3(SEQ / 128, BATCH * HEADS), 256, ATTN_SMEM>>>(q16, k16, v16, atth, attl);
    // 4) out-projection (split-bf16, fp32 out)
    gemm_hmma<0><<<dim3(DIM / 128, MROWS / 128), 256, GEMM_SMEM>>>(
        atth, attl, woh, wol, proj, nullptr, nullptr, nullptr, DIM, INNER);
    // 5) post-LN
    ln_kernel<<<MROWS, 256>>>(proj, onw, onb, out);
}

// round 7
// speedup vs baseline: 5.5828x; 1.1644x over previous
#include <cuda_runtime.h>
#include <cuda_bf16.h>
#include <cuda_fp16.h>
#include <cstdint>

#define BATCH 4
#define SEQ   2048
#define DIM   1024
#define HEADS 8
#define DHEAD 64
#define INNER 512
#define MROWS 8192
#define NQKV  640            // 512 (Q) + 64 (K) + 64 (V)
#define QK_SCALE 0.125f

typedef __nv_bfloat16 bf16;

// ---------------- scratch ----------------
__device__ bf16   g_xnh [MROWS * DIM];
__device__ bf16   g_xnl [MROWS * DIM];
__device__ __half g_q16 [MROWS * INNER];
__device__ __half g_k16 [MROWS * DHEAD];
__device__ __half g_v16 [MROWS * DHEAD];
__device__ __half g_att16[MROWS * INNER];
__device__ float  g_proj[MROWS * DIM];
__device__ bf16   g_w1h [NQKV * DIM], g_w1l [NQKV * DIM];   // [n][k]: Wq^T*s | Wkv^T
__device__ __half g_wo16[DIM * INNER];                      // [n][k] fp16

// ---------------- helpers ----------------
__device__ __forceinline__ uint32_t smem_u32(const void* p) {
    uint32_t a;
    asm("{ .reg .u64 t; cvta.to.shared.u64 t, %1; cvt.u32.u64 %0, t; }" : "=r"(a) : "l"(p));
    return a;
}
__device__ __forceinline__ void ldsm4(uint32_t* r, uint32_t a) {
    asm volatile("ldmatrix.sync.aligned.m8n8.x4.shared.b16 {%0,%1,%2,%3}, [%4];"
                 : "=r"(r[0]), "=r"(r[1]), "=r"(r[2]), "=r"(r[3]) : "r"(a));
}
__device__ __forceinline__ void ldsm4t(uint32_t* r, uint32_t a) {
    asm volatile("ldmatrix.sync.aligned.m8n8.x4.trans.shared.b16 {%0,%1,%2,%3}, [%4];"
                 : "=r"(r[0]), "=r"(r[1]), "=r"(r[2]), "=r"(r[3]) : "r"(a));
}
__device__ __forceinline__ void mma16816(float* d, const uint32_t* a, const uint32_t* b) {
    asm volatile(
        "mma.sync.aligned.m16n8k16.row.col.f32.bf16.bf16.f32 "
        "{%0,%1,%2,%3}, {%4,%5,%6,%7}, {%8,%9}, {%0,%1,%2,%3};"
        : "+f"(d[0]), "+f"(d[1]), "+f"(d[2]), "+f"(d[3])
        : "r"(a[0]), "r"(a[1]), "r"(a[2]), "r"(a[3]), "r"(b[0]), "r"(b[1]));
}
__device__ __forceinline__ void mma16816h(float* d, const uint32_t* a, const uint32_t* b) {
    asm volatile(
        "mma.sync.aligned.m16n8k16.row.col.f32.f16.f16.f32 "
        "{%0,%1,%2,%3}, {%4,%5,%6,%7}, {%8,%9}, {%0,%1,%2,%3};"
        : "+f"(d[0]), "+f"(d[1]), "+f"(d[2]), "+f"(d[3])
        : "r"(a[0]), "r"(a[1]), "r"(a[2]), "r"(a[3]), "r"(b[0]), "r"(b[1]));
}
__device__ __forceinline__ uint32_t packh(float lo, float hi) {
    uint32_t r;
    asm("cvt.rn.f16x2.f32 %0, %1, %2;" : "=r"(r) : "f"(hi), "f"(lo));
    return r;
}
__device__ __forceinline__ void cpa16(uint32_t dst, const void* src) {
    asm volatile("cp.async.cg.shared.global [%0], [%1], 16;" :: "r"(dst), "l"(src));
}
#define CP_COMMIT() asm volatile("cp.async.commit_group;" ::: "memory")
#define CP_WAIT1()  asm volatile("cp.async.wait_group 1;" ::: "memory")
#define CP_WAIT0()  asm volatile("cp.async.wait_group 0;" ::: "memory")

// ---------------- LayerNorm (fp32 out) ----------------
__global__ void ln_kernel(const float* __restrict__ x, const float* __restrict__ w,
                          const float* __restrict__ b, float* __restrict__ out) {
    const int row = blockIdx.x, t = threadIdx.x;
    const float4 v = ((const float4*)(x + (size_t)row * DIM))[t];
    float s = v.x + v.y + v.z + v.w;
    float sq = v.x*v.x + v.y*v.y + v.z*v.z + v.w*v.w;
    #pragma unroll
    for (int m = 16; m > 0; m >>= 1) {
        s += __shfl_xor_sync(~0u, s, m);  sq += __shfl_xor_sync(~0u, sq, m);
    }
    __shared__ float ss[8], ssq[8];
    const int wid = t >> 5, lane = t & 31;
    if (lane == 0) { ss[wid] = s; ssq[wid] = sq; }
    __syncthreads();
    if (wid == 0) {
        s = (lane < 8) ? ss[lane] : 0.f;  sq = (lane < 8) ? ssq[lane] : 0.f;
        #pragma unroll
        for (int m = 4; m > 0; m >>= 1) {
            s += __shfl_xor_sync(~0u, s, m);  sq += __shfl_xor_sync(~0u, sq, m);
        }
        if (lane == 0) { ss[0] = s; ssq[0] = sq; }
    }
    __syncthreads();
    const float mu = ss[0] * (1.0f / DIM);
    const float rstd = rsqrtf(ssq[0] * (1.0f / DIM) - mu * mu + 1e-5f);
    const float4 wv = ((const float4*)w)[t];
    const float4 bv = ((const float4*)b)[t];
    float4 o;
    o.x = (v.x - mu) * rstd * wv.x + bv.x;  o.y = (v.y - mu) * rstd * wv.y + bv.y;
    o.z = (v.z - mu) * rstd * wv.z + bv.z;  o.w = (v.w - mu) * rstd * wv.w + bv.w;
    ((float4*)(out + (size_t)row * DIM))[t] = o;
}

// ---------------- LayerNorm -> split bf16 ----------------
__global__ void ln_split_kernel(const float* __restrict__ x, const float* __restrict__ w,
                                const float* __restrict__ b,
                                bf16* __restrict__ oh, bf16* __restrict__ ol) {
    const int row = blockIdx.x, t = threadIdx.x;
    const float4 v = ((const float4*)(x + (size_t)row * DIM))[t];
    float s = v.x + v.y + v.z + v.w;
    float sq = v.x*v.x + v.y*v.y + v.z*v.z + v.w*v.w;
    #pragma unroll
    for (int m = 16; m > 0; m >>= 1) {
        s += __shfl_xor_sync(~0u, s, m);  sq += __shfl_xor_sync(~0u, sq, m);
    }
    __shared__ float ss[8], ssq[8];
    const int wid = t >> 5, lane = t & 31;
    if (lane == 0) { ss[wid] = s; ssq[wid] = sq; }
    __syncthreads();
    if (wid == 0) {
        s = (lane < 8) ? ss[lane] : 0.f;  sq = (lane < 8) ? ssq[lane] : 0.f;
        #pragma unroll
        for (int m = 4; m > 0; m >>= 1) {
            s += __shfl_xor_sync(~0u, s, m);  sq += __shfl_xor_sync(~0u, sq, m);
        }
        if (lane == 0) { ss[0] = s; ssq[0] = sq; }
    }
    __syncthreads();
    const float mu = ss[0] * (1.0f / DIM);
    const float rstd = rsqrtf(ssq[0] * (1.0f / DIM) - mu * mu + 1e-5f);
    const float4 wv = ((const float4*)w)[t];
    const float4 bv = ((const float4*)b)[t];
    float o[4];
    o[0] = (v.x - mu) * rstd * wv.x + bv.x;  o[1] = (v.y - mu) * rstd * wv.y + bv.y;
    o[2] = (v.z - mu) * rstd * wv.z + bv.z;  o[3] = (v.w - mu) * rstd * wv.w + bv.w;
    size_t base = (size_t)row * DIM + t * 4;
    #pragma unroll
    for (int j = 0; j < 4; j += 2) {
        bf16 h0 = __float2bfloat16(o[j]),     h1 = __float2bfloat16(o[j + 1]);
        bf16 l0 = __float2bfloat16(o[j] - __bfloat162float(h0));
        bf16 l1 = __float2bfloat16(o[j + 1] - __bfloat162float(h1));
        *(__nv_bfloat162*)(oh + base + j) = __halves2bfloat162(h0, h1);
        *(__nv_bfloat162*)(ol + base + j) = __halves2bfloat162(l0, l1);
    }
}

// ---------------- weight transpose + split (+scale): W[K,N] -> split bf16 [n][k] ----------------
__global__ void wtrans_kernel(const float* __restrict__ W, bf16* __restrict__ Th,
                              bf16* __restrict__ Tl, int K, int N, float scale) {
    __shared__ float tile[32][33];
    const int n0 = blockIdx.x * 32, k0 = blockIdx.y * 32;
    const int tx = threadIdx.x, ty = threadIdx.y;   // 32x8
    #pragma unroll
    for (int j = 0; j < 4; j++)
        tile[ty + 8 * j][tx] = W[(size_t)(k0 + ty + 8 * j) * N + n0 + tx];
    __syncthreads();
    #pragma unroll
    for (int j = 0; j < 4; j++) {
        float v = tile[tx][ty + 8 * j] * scale;
        bf16 h = __float2bfloat16(v);
        bf16 l = __float2bfloat16(v - __bfloat162float(h));
        size_t idx = (size_t)(n0 + ty + 8 * j) * K + k0 + tx;
        Th[idx] = h;  Tl[idx] = l;
    }
}

// ---------------- weight transpose fp16: W[K,N] -> [n][k] fp16 ----------------
__global__ void wtrans16_kernel(const float* __restrict__ W, __half* __restrict__ T16,
                                int K, int N) {
    __shared__ float tile[32][33];
    const int n0 = blockIdx.x * 32, k0 = blockIdx.y * 32;
    const int tx = threadIdx.x, ty = threadIdx.y;   // 32x8
    #pragma unroll
    for (int j = 0; j < 4; j++)
        tile[ty + 8 * j][tx] = W[(size_t)(k0 + ty + 8 * j) * N + n0 + tx];
    __syncthreads();
    #pragma unroll
    for (int j = 0; j < 4; j++)
        T16[(size_t)(n0 + ty + 8 * j) * K + k0 + tx] = __float2half(tile[tx][ty + 8 * j]);
}

// ---------------- HMMA split-bf16 GEMM (QKV): fused fp16 Q/K/V epilogue ----------------
#define GP 72                       // padded smem row (bf16 elems), 144 B
#define GARR  (128 * GP * 2)        // 18432 B per matrix
#define GSTG  (4 * GARR)            // 73728 B per stage
#define GEMM_SMEM (2 * GSTG)        // 147456 B

__global__ __launch_bounds__(256, 1)
void gemm_qkv(const bf16* __restrict__ Ah, const bf16* __restrict__ Al,
              const bf16* __restrict__ Bh, const bf16* __restrict__ Bl,
              __half* __restrict__ q16, __half* __restrict__ k16, __half* __restrict__ v16,
              int N, int K) {
    extern __shared__ char sm[];
    const int tid = threadIdx.x, lane = tid & 31, wid = tid >> 5;
    const int wm = wid >> 1, wn = wid & 1;
    const int bm = blockIdx.y * 128, bn = blockIdx.x * 128;
    const uint32_t sb = smem_u32(sm);

    const bf16* src[4] = {Ah, Al, Bh, Bl};
    const int   r0 [4] = {bm, bm, bn, bn};

    auto load_stage = [&](int st, int k0) {
        uint32_t base = sb + (uint32_t)st * GSTG;
        #pragma unroll
        for (int j = 0; j < 16; j++) {
            int arr = j >> 2;
            int within = tid + (j & 3) * 256;
            int r = within >> 3, ch = within & 7;
            cpa16(base + arr * GARR + r * 144 + ch * 16,
                  src[arr] + (size_t)(r0[arr] + r) * K + k0 + ch * 8);
        }
    };

    float d[2][8][4] = {};
    const int a_r = wm * 32 + (lane & 15), a_c = (lane >> 4) * 8;
    const int b_r = wn * 64 + (lane >> 4) * 8 + (lane & 7), b_c = ((lane >> 3) & 1) * 8;

    const int T = K / 64;
    load_stage(0, 0);
    CP_COMMIT();

    for (int it = 0; it < T; it++) {
        if (it + 1 < T) { load_stage((it + 1) & 1, (it + 1) * 64); CP_COMMIT(); CP_WAIT1(); }
        else            { CP_WAIT0(); }
        __syncthreads();

        const uint32_t stg = sb + (uint32_t)(it & 1) * GSTG;
        #pragma unroll
        for (int ks = 0; ks < 4; ks++) {
            uint32_t aH[2][4], aL[2][4];
            #pragma unroll
            for (int mi = 0; mi < 2; mi++) {
                uint32_t off = (uint32_t)((a_r + mi * 16) * GP + ks * 16 + a_c) * 2;
                ldsm4(aH[mi], stg + 0 * GARR + off);
                ldsm4(aL[mi], stg + 1 * GARR + off);
            }
            #pragma unroll
            for (int jp = 0; jp < 4; jp++) {
                uint32_t bH[4], bL[4];
                uint32_t off = (uint32_t)((jp * 16 + b_r) * GP + ks * 16 + b_c) * 2;
                ldsm4(bH, stg + 2 * GARR + off);
                ldsm4(bL, stg + 3 * GARR + off);
                #pragma unroll
                for (int mi = 0; mi < 2; mi++) {
                    mma16816(d[mi][2 * jp],     aH[mi], bH);
                    mma16816(d[mi][2 * jp],     aH[mi], bL);
                    mma16816(d[mi][2 * jp],     aL[mi], bH);
                    mma16816(d[mi][2 * jp + 1], aH[mi], bH + 2);
                    mma16816(d[mi][2 * jp + 1], aH[mi], bL + 2);
                    mma16816(d[mi][2 * jp + 1], aL[mi], bH + 2);
                }
            }
        }
        __syncthreads();
    }

    #pragma unroll
    for (int mi = 0; mi < 2; mi++) {
        int row = bm + wm * 32 + mi * 16 + (lane >> 2);
        #pragma unroll
        for (int jt = 0; jt < 8; jt++) {
            int col = bn + wn * 64 + jt * 8 + (lane & 3) * 2;
            #pragma unroll
            for (int rr = 0; rr < 2; rr++) {
                int r2 = row + rr * 8;
                __half2 hv = __floats2half2_rn(d[mi][jt][2 * rr], d[mi][jt][2 * rr + 1]);
                if (col < 512)      *(__half2*)(q16 + (size_t)r2 * INNER + col)         = hv;
                else if (col < 576) *(__half2*)(k16 + (size_t)r2 * DHEAD + (col - 512)) = hv;
                else                *(__half2*)(v16 + (size_t)r2 * DHEAD + (col - 576)) = hv;
            }
        }
    }
}

// ---------------- fp16 single-product GEMM (out-proj): C fp32 = A @ B^T ----------------
#define G2STG (2 * GARR)            // 36864 B per stage
#define GEMM16_SMEM (2 * G2STG)     // 73728 B

__global__ __launch_bounds__(256, 2)
void gemm_fp16(const __half* __restrict__ A, const __half* __restrict__ B,
               float* __restrict__ C, int N, int K) {
    extern __shared__ char sm[];
    const int tid = threadIdx.x, lane = tid & 31, wid = tid >> 5;
    const int wm = wid >> 1, wn = wid & 1;
    const int bm = blockIdx.y * 128, bn = blockIdx.x * 128;
    const uint32_t sb = smem_u32(sm);

    auto load_stage = [&](int st, int k0) {
        uint32_t base = sb + (uint32_t)st * G2STG;
        #pragma unroll
        for (int j = 0; j < 8; j++) {
            int arr = j >> 2;
            int within = tid + (j & 3) * 256;     // 0..1023 per array
            int r = within >> 3, ch = within & 7;
            const __half* srcp = (arr == 0)
                ? (A + (size_t)(bm + r) * K + k0 + ch * 8)
                : (B + (size_t)(bn + r) * K + k0 + ch * 8);
            cpa16(base + arr * GARR + r * 144 + ch * 16, srcp);
        }
    };

    float d[2][8][4] = {};
    const int a_r = wm * 32 + (lane & 15), a_c = (lane >> 4) * 8;
    const int b_r = wn * 64 + (lane >> 4) * 8 + (lane & 7), b_c = ((lane >> 3) & 1) * 8;

    const int T = K / 64;
    load_stage(0, 0);
    CP_COMMIT();

    for (int it = 0; it < T; it++) {
        if (it + 1 < T) { load_stage((it + 1) & 1, (it + 1) * 64); CP_COMMIT(); CP_WAIT1(); }
        else            { CP_WAIT0(); }
        __syncthreads();

        const uint32_t stg = sb + (uint32_t)(it & 1) * G2STG;
        #pragma unroll
        for (int ks = 0; ks < 4; ks++) {
            uint32_t aF[2][4];
            #pragma unroll
            for (int mi = 0; mi < 2; mi++)
                ldsm4(aF[mi], stg + (uint32_t)((a_r + mi * 16) * GP + ks * 16 + a_c) * 2);
            #pragma unroll
            for (int jp = 0; jp < 4; jp++) {
                uint32_t bF[4];
                ldsm4(bF, stg + GARR + (uint32_t)((jp * 16 + b_r) * GP + ks * 16 + b_c) * 2);
                #pragma unroll
                for (int mi = 0; mi < 2; mi++) {
                    mma16816h(d[mi][2 * jp],     aF[mi], bF);
                    mma16816h(d[mi][2 * jp + 1], aF[mi], bF + 2);
                }
            }
        }
        __syncthreads();
    }

    #pragma unroll
    for (int mi = 0; mi < 2; mi++) {
        int row = bm + wm * 32 + mi * 16 + (lane >> 2);
        #pragma unroll
        for (int jt = 0; jt < 8; jt++) {
            int col = bn + wn * 64 + jt * 8 + (lane & 3) * 2;
            *(float2*)(C + (size_t)row * N + col)       = make_float2(d[mi][jt][0], d[mi][jt][1]);
            *(float2*)(C + (size_t)(row + 8) * N + col) = make_float2(d[mi][jt][2], d[mi][jt][3]);
        }
    }
}

// ---------------- HMMA flash attention: fp16 QK single-product, fp16 PV ----------------
#define AQSZ  18432
#define AKV   9216
#define ASTG2 (2 * AKV)
#define ATTN_SMEM (AQSZ + 2 * ASTG2)   // 55296

__global__ __launch_bounds__(256, 2)
void attn_hmma(const __half* __restrict__ Q16, const __half* __restrict__ K16,
               const __half* __restrict__ V16, __half* __restrict__ O16) {
    extern __shared__ char sm[];
    const int tid = threadIdx.x, lane = tid & 31, wid = tid >> 5;
    const int qt = blockIdx.x, bh = blockIdx.y;
    const int b = bh >> 3, h = bh & 7;
    const int qrow0 = b * SEQ + qt * 128;
    const int krow0 = b * SEQ;
    const uint32_t sb = smem_u32(sm);

    // load Q tile (128 x 64 fp16) into padded smem
    #pragma unroll
    for (int j = 0; j < 4; j++) {
        int within = tid + j * 256;               // 0..1023
        int r = within >> 3, ch = within & 7;
        *(uint4*)(sm + r * 144 + ch * 16) =
            *(const uint4*)(Q16 + (size_t)(qrow0 + r) * INNER + h * DHEAD + ch * 8);
    }

    auto load_kv = [&](int st, int kt) {
        uint32_t base = sb + AQSZ + (uint32_t)st * ASTG2;
        int krow = krow0 + kt * 64;
        #pragma unroll
        for (int j = 0; j < 4; j++) {
            int arr = j >> 1;
            int within = tid + (j & 1) * 256;     // 0..511 per array
            int r = within >> 3, ch = within & 7;
            const __half* srcp = (arr == 0)
                ? (K16 + (size_t)(krow + r) * DHEAD + ch * 8)
                : (V16 + (size_t)(krow + r) * DHEAD + ch * 8);
            cpa16(base + arr * AKV + r * 144 + ch * 16, srcp);
        }
    };

    const int rbase = wid * 16;
    const int a_r = rbase + (lane & 15), a_c = (lane >> 4) * 8;
    const int b_r = (lane >> 4) * 8 + (lane & 7), b_c = ((lane >> 3) & 1) * 8;
    const int v_r = ((lane >> 3) & 1) * 8 + (lane & 7), v_c = (lane >> 4) * 8;

    float o[8][4] = {};
    float mreg[2] = {-1e30f, -1e30f}, lreg[2] = {0.f, 0.f};

    const int T = SEQ / 64;
    load_kv(0, 0);
    CP_COMMIT();

    for (int kt = 0; kt < T; kt++) {
        if (kt + 1 < T) { load_kv((kt + 1) & 1, kt + 1); CP_COMMIT(); CP_WAIT1(); }
        else            { CP_WAIT0(); }
        __syncthreads();

        const uint32_t stg = sb + AQSZ + (uint32_t)(kt & 1) * ASTG2;

        // S = Q @ K^T (single fp16 product)
        float s[8][4] = {};
        #pragma unroll
        for (int dk = 0; dk < 4; dk++) {
            uint32_t aQ[4];
            ldsm4(aQ, sb + (uint32_t)(a_r * GP + dk * 16 + a_c) * 2);
            #pragma unroll
            for (int jp = 0; jp < 4; jp++) {
                uint32_t bK[4];
                ldsm4(bK, stg + (uint32_t)((jp * 16 + b_r) * GP + dk * 16 + b_c) * 2);
                mma16816h(s[2 * jp],     aQ, bK);
                mma16816h(s[2 * jp + 1], aQ, bK + 2);
            }
        }

        // online softmax
        #pragma unroll
        for (int e = 0; e < 2; e++) {
            float rmax = -1e30f;
            #pragma unroll
            for (int jt = 0; jt < 8; jt++)
                rmax = fmaxf(rmax, fmaxf(s[jt][2 * e], s[jt][2 * e + 1]));
            rmax = fmaxf(rmax, __shfl_xor_sync(~0u, rmax, 1));
            rmax = fmaxf(rmax, __shfl_xor_sync(~0u, rmax, 2));
            float mn = fmaxf(mreg[e], rmax);
            float corr = __expf(mreg[e] - mn);
            mreg[e] = mn;
            float rsum = 0.f;
            #pragma unroll
            for (int jt = 0; jt < 8; jt++) {
                s[jt][2 * e]     = __expf(s[jt][2 * e] - mn);
                s[jt][2 * e + 1] = __expf(s[jt][2 * e + 1] - mn);
                rsum += s[jt][2 * e] + s[jt][2 * e + 1];
            }
            rsum += __shfl_xor_sync(~0u, rsum, 1);
            rsum += __shfl_xor_sync(~0u, rsum, 2);
            lreg[e] = lreg[e] * corr + rsum;
            #pragma unroll
            for (int jt = 0; jt < 8; jt++) { o[jt][2 * e] *= corr; o[jt][2 * e + 1] *= corr; }
        }

        // O += P @ V  (fp16)
        #pragma unroll
        for (int kk = 0; kk < 4; kk++) {
            uint32_t aP[4] = {
                packh(s[2 * kk][0],     s[2 * kk][1]),
                packh(s[2 * kk][2],     s[2 * kk][3]),
                packh(s[2 * kk + 1][0], s[2 * kk + 1][1]),
                packh(s[2 * kk + 1][2], s[2 * kk + 1][3])
            };
            #pragma unroll
            for (int dp = 0; dp < 4; dp++) {
                uint32_t bV[4];
                ldsm4t(bV, stg + AKV + (uint32_t)((kk * 16 + v_r) * GP + dp * 16 + v_c) * 2);
                mma16816h(o[2 * dp],     aP, bV);
                mma16816h(o[2 * dp + 1], aP, bV + 2);
            }
        }
        __syncthreads();
    }

    // epilogue: normalize, fp16 store
    #pragma unroll
    for (int e = 0; e < 2; e++) {
        float inv = 1.0f / lreg[e];
        int row = qrow0 + rbase + (lane >> 2) + 8 * e;
        #pragma unroll
        for (int dd = 0; dd < 8; dd++) {
            size_t base = (size_t)row * INNER + h * DHEAD + dd * 8 + (lane & 3) * 2;
            *(uint32_t*)(O16 + base) = packh(o[dd][2 * e] * inv, o[dd][2 * e + 1] * inv);
        }
    }
}

// ---------------- launch ----------------
extern "C" void kernel_launch(void* const* d_in, const int* in_sizes, int n_in,
                              void* d_out, int out_size) {
    const float* x   = (const float*)d_in[0];
    const float* Wq  = (const float*)d_in[1];
    const float* Wkv = (const float*)d_in[2];
    const float* Wo  = (const float*)d_in[3];
    const float* nw  = (const float*)d_in[4];
    const float* nb  = (const float*)d_in[5];
    const float* onw = (const float*)d_in[6];
    const float* onb = (const float*)d_in[7];
    float* out = (float*)d_out;

    bf16 *xnh, *xnl, *w1h, *w1l;
    __half *q16, *k16, *v16, *att16, *wo16;
    float *proj;
    cudaGetSymbolAddress((void**)&xnh,   g_xnh);
    cudaGetSymbolAddress((void**)&xnl,   g_xnl);
    cudaGetSymbolAddress((void**)&q16,   g_q16);
    cudaGetSymbolAddress((void**)&k16,   g_k16);
    cudaGetSymbolAddress((void**)&v16,   g_v16);
    cudaGetSymbolAddress((void**)&att16, g_att16);
    cudaGetSymbolAddress((void**)&proj,  g_proj);
    cudaGetSymbolAddress((void**)&w1h,   g_w1h);
    cudaGetSymbolAddress((void**)&w1l,   g_w1l);
    cudaGetSymbolAddress((void**)&wo16,  g_wo16);

    cudaFuncSetAttribute(gemm_qkv,  cudaFuncAttributeMaxDynamicSharedMemorySize, GEMM_SMEM);
    cudaFuncSetAttribute(gemm_fp16, cudaFuncAttributeMaxDynamicSharedMemorySize, GEMM16_SMEM);
    cudaFuncSetAttribute(attn_hmma, cudaFuncAttributeMaxDynamicSharedMemorySize, ATTN_SMEM);

    // weight transpose (+fold QK scale into Wq); Wo -> fp16
    wtrans_kernel<<<dim3(INNER / 32, DIM / 32), dim3(32, 8)>>>(Wq, w1h, w1l, DIM, INNER, QK_SCALE);
    wtrans_kernel<<<dim3(128 / 32, DIM / 32), dim3(32, 8)>>>(Wkv, w1h + (size_t)512 * DIM,
                                                             w1l + (size_t)512 * DIM, DIM, 128, 1.0f);
    wtrans16_kernel<<<dim3(DIM / 32, INNER / 32), dim3(32, 8)>>>(Wo, wo16, INNER, DIM);

    // 1) pre-LN -> split bf16
    ln_split_kernel<<<MROWS, 256>>>(x, nw, nb, xnh, xnl);
    // 2) merged QKV GEMM (split-bf16, fused fp16 epilogue)
    gemm_qkv<<<dim3(NQKV / 128, MROWS / 128), 256, GEMM_SMEM>>>(
        xnh, xnl, w1h, w1l, q16, k16, v16, NQKV, DIM);
    // 3) flash attention (fp16 all the way) -> fp16 att
    attn_hmma<<<dim3(SEQ / 128, BATCH * HEADS), 256, ATTN_SMEM>>>(q16, k16, v16, att16);
    // 4) out-projection (fp16 single product)
    gemm_fp16<<<dim3(DIM / 128, MROWS / 128), 256, GEMM16_SMEM>>>(att16, wo16, proj, DIM, INNER);
    // 5) post-LN
    ln_kernel<<<MROWS, 256>>>(proj, onw, onb, out);
}

// round 8
// speedup vs baseline: 7.5672x; 1.3554x over previous
#include <cuda_runtime.h>
#include <cuda_bf16.h>
#include <cuda_fp16.h>
#include <cstdint>

#define BATCH 4
#define SEQ   2048
#define DIM   1024
#define HEADS 8
#define DHEAD 64
#define INNER 512
#define MROWS 8192
#define NQKV  640            // 512 (Q) + 64 (K) + 64 (V)
#define QK_SCALE 0.125f
#define LOG2E    1.44269504088896f

typedef __nv_bfloat16 bf16;

// ---------------- scratch ----------------
__device__ __half g_xn16[MROWS * DIM];
__device__ __half g_q16 [MROWS * INNER];
__device__ __half g_k16 [MROWS * DHEAD];
__device__ __half g_v16 [MROWS * DHEAD];
__device__ __half g_att16[MROWS * INNER];
__device__ float  g_proj[MROWS * DIM];
__device__ __half g_w116[NQKV * DIM];     // [n][k]: Wq^T*(s*log2e) | Wkv^T
__device__ __half g_wo16[DIM * INNER];    // [n][k]

// ---------------- helpers ----------------
__device__ __forceinline__ uint32_t smem_u32(const void* p) {
    uint32_t a;
    asm("{ .reg .u64 t; cvta.to.shared.u64 t, %1; cvt.u32.u64 %0, t; }" : "=r"(a) : "l"(p));
    return a;
}
__device__ __forceinline__ void ldsm4(uint32_t* r, uint32_t a) {
    asm volatile("ldmatrix.sync.aligned.m8n8.x4.shared.b16 {%0,%1,%2,%3}, [%4];"
                 : "=r"(r[0]), "=r"(r[1]), "=r"(r[2]), "=r"(r[3]) : "r"(a));
}
__device__ __forceinline__ void ldsm4t(uint32_t* r, uint32_t a) {
    asm volatile("ldmatrix.sync.aligned.m8n8.x4.trans.shared.b16 {%0,%1,%2,%3}, [%4];"
                 : "=r"(r[0]), "=r"(r[1]), "=r"(r[2]), "=r"(r[3]) : "r"(a));
}
__device__ __forceinline__ void mma16816h(float* d, const uint32_t* a, const uint32_t* b) {
    asm volatile(
        "mma.sync.aligned.m16n8k16.row.col.f32.f16.f16.f32 "
        "{%0,%1,%2,%3}, {%4,%5,%6,%7}, {%8,%9}, {%0,%1,%2,%3};"
        : "+f"(d[0]), "+f"(d[1]), "+f"(d[2]), "+f"(d[3])
        : "r"(a[0]), "r"(a[1]), "r"(a[2]), "r"(a[3]), "r"(b[0]), "r"(b[1]));
}
__device__ __forceinline__ uint32_t packh(float lo, float hi) {
    uint32_t r;
    asm("cvt.rn.f16x2.f32 %0, %1, %2;" : "=r"(r) : "f"(hi), "f"(lo));
    return r;
}
__device__ __forceinline__ void cpa16(uint32_t dst, const void* src) {
    asm volatile("cp.async.cg.shared.global [%0], [%1], 16;" :: "r"(dst), "l"(src));
}
#define CP_COMMIT() asm volatile("cp.async.commit_group;" ::: "memory")
#define CP_WAIT1()  asm volatile("cp.async.wait_group 1;" ::: "memory")
#define CP_WAIT0()  asm volatile("cp.async.wait_group 0;" ::: "memory")

// ---------------- LayerNorm (fp32 out) ----------------
__global__ void ln_kernel(const float* __restrict__ x, const float* __restrict__ w,
                          const float* __restrict__ b, float* __restrict__ out) {
    const int row = blockIdx.x, t = threadIdx.x;
    const float4 v = ((const float4*)(x + (size_t)row * DIM))[t];
    float s = v.x + v.y + v.z + v.w;
    float sq = v.x*v.x + v.y*v.y + v.z*v.z + v.w*v.w;
    #pragma unroll
    for (int m = 16; m > 0; m >>= 1) {
        s += __shfl_xor_sync(~0u, s, m);  sq += __shfl_xor_sync(~0u, sq, m);
    }
    __shared__ float ss[8], ssq[8];
    const int wid = t >> 5, lane = t & 31;
    if (lane == 0) { ss[wid] = s; ssq[wid] = sq; }
    __syncthreads();
    if (wid == 0) {
        s = (lane < 8) ? ss[lane] : 0.f;  sq = (lane < 8) ? ssq[lane] : 0.f;
        #pragma unroll
        for (int m = 4; m > 0; m >>= 1) {
            s += __shfl_xor_sync(~0u, s, m);  sq += __shfl_xor_sync(~0u, sq, m);
        }
        if (lane == 0) { ss[0] = s; ssq[0] = sq; }
    }
    __syncthreads();
    const float mu = ss[0] * (1.0f / DIM);
    const float rstd = rsqrtf(ssq[0] * (1.0f / DIM) - mu * mu + 1e-5f);
    const float4 wv = ((const float4*)w)[t];
    const float4 bv = ((const float4*)b)[t];
    float4 o;
    o.x = (v.x - mu) * rstd * wv.x + bv.x;  o.y = (v.y - mu) * rstd * wv.y + bv.y;
    o.z = (v.z - mu) * rstd * wv.z + bv.z;  o.w = (v.w - mu) * rstd * wv.w + bv.w;
    ((float4*)(out + (size_t)row * DIM))[t] = o;
}

// ---------------- LayerNorm -> fp16 ----------------
__global__ void ln16_kernel(const float* __restrict__ x, const float* __restrict__ w,
                            const float* __restrict__ b, __half* __restrict__ o16) {
    const int row = blockIdx.x, t = threadIdx.x;
    const float4 v = ((const float4*)(x + (size_t)row * DIM))[t];
    float s = v.x + v.y + v.z + v.w;
    float sq = v.x*v.x + v.y*v.y + v.z*v.z + v.w*v.w;
    #pragma unroll
    for (int m = 16; m > 0; m >>= 1) {
        s += __shfl_xor_sync(~0u, s, m);  sq += __shfl_xor_sync(~0u, sq, m);
    }
    __shared__ float ss[8], ssq[8];
    const int wid = t >> 5, lane = t & 31;
    if (lane == 0) { ss[wid] = s; ssq[wid] = sq; }
    __syncthreads();
    if (wid == 0) {
        s = (lane < 8) ? ss[lane] : 0.f;  sq = (lane < 8) ? ssq[lane] : 0.f;
        #pragma unroll
        for (int m = 4; m > 0; m >>= 1) {
            s += __shfl_xor_sync(~0u, s, m);  sq += __shfl_xor_sync(~0u, sq, m);
        }
        if (lane == 0) { ss[0] = s; ssq[0] = sq; }
    }
    __syncthreads();
    const float mu = ss[0] * (1.0f / DIM);
    const float rstd = rsqrtf(ssq[0] * (1.0f / DIM) - mu * mu + 1e-5f);
    const float4 wv = ((const float4*)w)[t];
    const float4 bv = ((const float4*)b)[t];
    size_t base = (size_t)row * DIM + t * 4;
    *(__half2*)(o16 + base) = __floats2half2_rn((v.x - mu) * rstd * wv.x + bv.x,
                                                (v.y - mu) * rstd * wv.y + bv.y);
    *(__half2*)(o16 + base + 2) = __floats2half2_rn((v.z - mu) * rstd * wv.z + bv.z,
                                                    (v.w - mu) * rstd * wv.w + bv.w);
}

// ---------------- weight transpose fp16 (+scale): W[K,N] -> [n][k] fp16 ----------------
__global__ void wtrans16_kernel(const float* __restrict__ W, __half* __restrict__ T16,
                                int K, int N, float scale) {
    __shared__ float tile[32][33];
    const int n0 = blockIdx.x * 32, k0 = blockIdx.y * 32;
    const int tx = threadIdx.x, ty = threadIdx.y;   // 32x8
    #pragma unroll
    for (int j = 0; j < 4; j++)
        tile[ty + 8 * j][tx] = W[(size_t)(k0 + ty + 8 * j) * N + n0 + tx];
    __syncthreads();
    #pragma unroll
    for (int j = 0; j < 4; j++)
        T16[(size_t)(n0 + ty + 8 * j) * K + k0 + tx] =
            __float2half(tile[tx][ty + 8 * j] * scale);
}

// ---------------- fp16 single-product GEMM ----------------
// C[M,N] = A @ B^T.  MODE 0: fp32 C.  MODE 1: fp16 scatter to q/k/v.
#define GP 72                       // padded smem row (fp16 elems), 144 B
#define GARR  (128 * GP * 2)        // 18432 B per matrix
#define G2STG (2 * GARR)            // 36864 B per stage
#define GEMM16_SMEM (2 * G2STG)     // 73728 B

template<int MODE>
__global__ __launch_bounds__(256, 2)
void gemm_fp16(const __half* __restrict__ A, const __half* __restrict__ B,
               float* __restrict__ C,
               __half* __restrict__ q16, __half* __restrict__ k16, __half* __restrict__ v16,
               int N, int K) {
    extern __shared__ char sm[];
    const int tid = threadIdx.x, lane = tid & 31, wid = tid >> 5;
    const int wm = wid >> 1, wn = wid & 1;
    const int bm = blockIdx.y * 128, bn = blockIdx.x * 128;
    const uint32_t sb = smem_u32(sm);

    auto load_stage = [&](int st, int k0) {
        uint32_t base = sb + (uint32_t)st * G2STG;
        #pragma unroll
        for (int j = 0; j < 8; j++) {
            int arr = j >> 2;
            int within = tid + (j & 3) * 256;     // 0..1023 per array
            int r = within >> 3, ch = within & 7;
            const __half* srcp = (arr == 0)
                ? (A + (size_t)(bm + r) * K + k0 + ch * 8)
                : (B + (size_t)(bn + r) * K + k0 + ch * 8);
            cpa16(base + arr * GARR + r * 144 + ch * 16, srcp);
        }
    };

    float d[2][8][4] = {};
    const int a_r = wm * 32 + (lane & 15), a_c = (lane >> 4) * 8;
    const int b_r = wn * 64 + (lane >> 4) * 8 + (lane & 7), b_c = ((lane >> 3) & 1) * 8;

    const int T = K / 64;
    load_stage(0, 0);
    CP_COMMIT();

    for (int it = 0; it < T; it++) {
        if (it + 1 < T) { load_stage((it + 1) & 1, (it + 1) * 64); CP_COMMIT(); CP_WAIT1(); }
        else            { CP_WAIT0(); }
        __syncthreads();

        const uint32_t stg = sb + (uint32_t)(it & 1) * G2STG;
        #pragma unroll
        for (int ks = 0; ks < 4; ks++) {
            uint32_t aF[2][4];
            #pragma unroll
            for (int mi = 0; mi < 2; mi++)
                ldsm4(aF[mi], stg + (uint32_t)((a_r + mi * 16) * GP + ks * 16 + a_c) * 2);
            #pragma unroll
            for (int jp = 0; jp < 4; jp++) {
                uint32_t bF[4];
                ldsm4(bF, stg + GARR + (uint32_t)((jp * 16 + b_r) * GP + ks * 16 + b_c) * 2);
                #pragma unroll
                for (int mi = 0; mi < 2; mi++) {
                    mma16816h(d[mi][2 * jp],     aF[mi], bF);
                    mma16816h(d[mi][2 * jp + 1], aF[mi], bF + 2);
                }
            }
        }
        __syncthreads();
    }

    #pragma unroll
    for (int mi = 0; mi < 2; mi++) {
        int row = bm + wm * 32 + mi * 16 + (lane >> 2);
        #pragma unroll
        for (int jt = 0; jt < 8; jt++) {
            int col = bn + wn * 64 + jt * 8 + (lane & 3) * 2;
            if (MODE == 0) {
                *(float2*)(C + (size_t)row * N + col)       = make_float2(d[mi][jt][0], d[mi][jt][1]);
                *(float2*)(C + (size_t)(row + 8) * N + col) = make_float2(d[mi][jt][2], d[mi][jt][3]);
            } else {
                #pragma unroll
                for (int rr = 0; rr < 2; rr++) {
                    int r2 = row + rr * 8;
                    __half2 hv = __floats2half2_rn(d[mi][jt][2 * rr], d[mi][jt][2 * rr + 1]);
                    if (col < 512)      *(__half2*)(q16 + (size_t)r2 * INNER + col)         = hv;
                    else if (col < 576) *(__half2*)(k16 + (size_t)r2 * DHEAD + (col - 512)) = hv;
                    else                *(__half2*)(v16 + (size_t)r2 * DHEAD + (col - 576)) = hv;
                }
            }
        }
    }
}

// ---------------- HMMA flash attention: fp16, exp2-domain softmax, 3-stage ----------------
#define AQSZ  18432
#define AKV   9216
#define ASTG2 (2 * AKV)
#define ATTN_SMEM (AQSZ + 3 * ASTG2)   // 73728

__global__ __launch_bounds__(256, 2)
void attn_hmma(const __half* __restrict__ Q16, const __half* __restrict__ K16,
               const __half* __restrict__ V16, __half* __restrict__ O16) {
    extern __shared__ char sm[];
    const int tid = threadIdx.x, lane = tid & 31, wid = tid >> 5;
    const int qt = blockIdx.x, bh = blockIdx.y;
    const int b = bh >> 3, h = bh & 7;
    const int qrow0 = b * SEQ + qt * 128;
    const int krow0 = b * SEQ;
    const uint32_t sb = smem_u32(sm);

    // load Q tile (128 x 64 fp16) into padded smem (scores come out in log2e domain)
    #pragma unroll
    for (int j = 0; j < 4; j++) {
        int within = tid + j * 256;               // 0..1023
        int r = within >> 3, ch = within & 7;
        *(uint4*)(sm + r * 144 + ch * 16) =
            *(const uint4*)(Q16 + (size_t)(qrow0 + r) * INNER + h * DHEAD + ch * 8);
    }

    auto load_kv = [&](int st, int kt) {
        uint32_t base = sb + AQSZ + (uint32_t)st * ASTG2;
        int krow = krow0 + kt * 64;
        #pragma unroll
        for (int j = 0; j < 4; j++) {
            int arr = j >> 1;
            int within = tid + (j & 1) * 256;     // 0..511 per array
            int r = within >> 3, ch = within & 7;
            const __half* srcp = (arr == 0)
                ? (K16 + (size_t)(krow + r) * DHEAD + ch * 8)
                : (V16 + (size_t)(krow + r) * DHEAD + ch * 8);
            cpa16(base + arr * AKV + r * 144 + ch * 16, srcp);
        }
    };

    const int rbase = wid * 16;
    const int a_r = rbase + (lane & 15), a_c = (lane >> 4) * 8;
    const int b_r = (lane >> 4) * 8 + (lane & 7), b_c = ((lane >> 3) & 1) * 8;
    const int v_r = ((lane >> 3) & 1) * 8 + (lane & 7), v_c = (lane >> 4) * 8;

    float o[8][4] = {};
    float mreg[2] = {-1e30f, -1e30f}, lreg[2] = {0.f, 0.f};

    const int T = SEQ / 64;   // 32
    load_kv(0, 0); CP_COMMIT();
    load_kv(1, 1); CP_COMMIT();

    for (int kt = 0; kt < T; kt++) {
        if (kt + 1 < T) CP_WAIT1(); else CP_WAIT0();
        __syncthreads();
        if (kt + 2 < T) { load_kv((kt + 2) % 3, kt + 2); CP_COMMIT(); }

        const uint32_t stg = sb + AQSZ + (uint32_t)(kt % 3) * ASTG2;

        // S' = Q' @ K^T  (log2e-scaled scores, single fp16 product)
        float s[8][4] = {};
        #pragma unroll
        for (int dk = 0; dk < 4; dk++) {
            uint32_t aQ[4];
            ldsm4(aQ, sb + (uint32_t)(a_r * GP + dk * 16 + a_c) * 2);
            #pragma unroll
            for (int jp = 0; jp < 4; jp++) {
                uint32_t bK[4];
                ldsm4(bK, stg + (uint32_t)((jp * 16 + b_r) * GP + dk * 16 + b_c) * 2);
                mma16816h(s[2 * jp],     aQ, bK);
                mma16816h(s[2 * jp + 1], aQ, bK + 2);
            }
        }

        // online softmax in exp2 domain
        #pragma unroll
        for (int e = 0; e < 2; e++) {
            float rmax = -1e30f;
            #pragma unroll
            for (int jt = 0; jt < 8; jt++)
                rmax = fmaxf(rmax, fmaxf(s[jt][2 * e], s[jt][2 * e + 1]));
            rmax = fmaxf(rmax, __shfl_xor_sync(~0u, rmax, 1));
            rmax = fmaxf(rmax, __shfl_xor_sync(~0u, rmax, 2));
            float mn = fmaxf(mreg[e], rmax);
            float corr = exp2f(mreg[e] - mn);
            mreg[e] = mn;
            float rsum = 0.f;
            #pragma unroll
            for (int jt = 0; jt < 8; jt++) {
                s[jt][2 * e]     = exp2f(s[jt][2 * e] - mn);
                s[jt][2 * e + 1] = exp2f(s[jt][2 * e + 1] - mn);
                rsum += s[jt][2 * e] + s[jt][2 * e + 1];
            }
            rsum += __shfl_xor_sync(~0u, rsum, 1);
            rsum += __shfl_xor_sync(~0u, rsum, 2);
            lreg[e] = lreg[e] * corr + rsum;
            #pragma unroll
            for (int jt = 0; jt < 8; jt++) { o[jt][2 * e] *= corr; o[jt][2 * e + 1] *= corr; }
        }

        // O += P @ V  (fp16)
        #pragma unroll
        for (int kk = 0; kk < 4; kk++) {
            uint32_t aP[4] = {
                packh(s[2 * kk][0],     s[2 * kk][1]),
                packh(s[2 * kk][2],     s[2 * kk][3]),
                packh(s[2 * kk + 1][0], s[2 * kk + 1][1]),
                packh(s[2 * kk + 1][2], s[2 * kk + 1][3])
            };
            #pragma unroll
            for (int dp = 0; dp < 4; dp++) {
                uint32_t bV[4];
                ldsm4t(bV, stg + AKV + (uint32_t)((kk * 16 + v_r) * GP + dp * 16 + v_c) * 2);
                mma16816h(o[2 * dp],     aP, bV);
                mma16816h(o[2 * dp + 1], aP, bV + 2);
            }
        }
    }

    // epilogue: normalize, fp16 store
    #pragma unroll
    for (int e = 0; e < 2; e++) {
        float inv = 1.0f / lreg[e];
        int row = qrow0 + rbase + (lane >> 2) + 8 * e;
        #pragma unroll
        for (int dd = 0; dd < 8; dd++) {
            size_t base = (size_t)row * INNER + h * DHEAD + dd * 8 + (lane & 3) * 2;
            *(uint32_t*)(O16 + base) = packh(o[dd][2 * e] * inv, o[dd][2 * e + 1] * inv);
        }
    }
}

// ---------------- launch ----------------
extern "C" void kernel_launch(void* const* d_in, const int* in_sizes, int n_in,
                              void* d_out, int out_size) {
    const float* x   = (const float*)d_in[0];
    const float* Wq  = (const float*)d_in[1];
    const float* Wkv = (const float*)d_in[2];
    const float* Wo  = (const float*)d_in[3];
    const float* nw  = (const float*)d_in[4];
    const float* nb  = (const float*)d_in[5];
    const float* onw = (const float*)d_in[6];
    const float* onb = (const float*)d_in[7];
    float* out = (float*)d_out;

    __half *xn16, *q16, *k16, *v16, *att16, *w116, *wo16;
    float *proj;
    cudaGetSymbolAddress((void**)&xn16,  g_xn16);
    cudaGetSymbolAddress((void**)&q16,   g_q16);
    cudaGetSymbolAddress((void**)&k16,   g_k16);
    cudaGetSymbolAddress((void**)&v16,   g_v16);
    cudaGetSymbolAddress((void**)&att16, g_att16);
    cudaGetSymbolAddress((void**)&proj,  g_proj);
    cudaGetSymbolAddress((void**)&w116,  g_w116);
    cudaGetSymbolAddress((void**)&wo16,  g_wo16);

    cudaFuncSetAttribute(gemm_fp16<0>, cudaFuncAttributeMaxDynamicSharedMemorySize, GEMM16_SMEM);
    cudaFuncSetAttribute(gemm_fp16<1>, cudaFuncAttributeMaxDynamicSharedMemorySize, GEMM16_SMEM);
    cudaFuncSetAttribute(attn_hmma,    cudaFuncAttributeMaxDynamicSharedMemorySize, ATTN_SMEM);

    // weight transpose -> fp16 (fold QK scale * log2e into Wq)
    wtrans16_kernel<<<dim3(INNER / 32, DIM / 32), dim3(32, 8)>>>(Wq, w116, DIM, INNER,
                                                                 QK_SCALE * LOG2E);
    wtrans16_kernel<<<dim3(128 / 32, DIM / 32), dim3(32, 8)>>>(Wkv, w116 + (size_t)512 * DIM,
                                                               DIM, 128, 1.0f);
    wtrans16_kernel<<<dim3(DIM / 32, INNER / 32), dim3(32, 8)>>>(Wo, wo16, INNER, DIM, 1.0f);

    // 1) pre-LN -> fp16
    ln16_kernel<<<MROWS, 256>>>(x, nw, nb, xn16);
    // 2) merged QKV GEMM (fp16 single product, fused q/k/v epilogue)
    gemm_fp16<1><<<dim3(NQKV / 128, MROWS / 128), 256, GEMM16_SMEM>>>(
        xn16, w116, nullptr, q16, k16, v16, NQKV, DIM);
    // 3) flash attention (fp16, exp2 softmax) -> fp16 att
    attn_hmma<<<dim3(SEQ / 128, BATCH * HEADS), 256, ATTN_SMEM>>>(q16, k16, v16, att16);
    // 4) out-projection (fp16 single product)
    gemm_fp16<0><<<dim3(DIM / 128, MROWS / 128), 256, GEMM16_SMEM>>>(
        att16, wo16, proj, nullptr, nullptr, nullptr, DIM, INNER);
    // 5) post-LN
    ln_kernel<<<MROWS, 256>>>(proj, onw, onb, out);
}